// round 10
// baseline (speedup 1.0000x reference)
#include <cuda_runtime.h>
#include <cstdint>

#define NB 8
#define NL 2048
#define ND 64
#define SCAP 256
#define STHRESH 35.0f
#define NITER 100
#define RMAX 12           // register-resident entries per row in iterate

// ---------------- static device scratch (no runtime allocation) ----------------
static __device__ float    d_P[(size_t)NB * NL * NL];   // dense scores (134 MB), reused self & cross
static __device__ unsigned d_mA[NB * NL];               // encoded row max (self)
static __device__ unsigned d_mC[NB * NL];               // encoded row max (cross)
static __device__ float    d_rbA[NB * NL];              // -0.5*||pos||^2
static __device__ float    d_cbA[NB * NL];              // lw - 0.5*||pos||^2
static __device__ float    d_rbC[NB * NL];              // -0.5*||tpos||^2
static __device__ float    d_cbC[NB * NL];              // lw + f - 0.5*||pos||^2 (after iterate)
static __device__ int      d_scnt[NB * NL];             // nnz per row
// transposed sparse lists: entry j of row r at [(b*SCAP + j)*NL + r]  (coalesced across rows)
static __device__ float          d_svalT[(size_t)NB * SCAP * NL];
static __device__ unsigned short d_scolT[(size_t)NB * SCAP * NL];
static __device__ float    d_gw[NB * NL];               // g * exp(tlw) partials

// monotone float<->uint encoding for atomicMax on floats (any sign)
__device__ __forceinline__ unsigned fenc(float f) {
    unsigned u = __float_as_uint(f);
    return (u & 0x80000000u) ? ~u : (u | 0x80000000u);
}
__device__ __forceinline__ float fdec(unsigned e) {
    return __uint_as_float((e & 0x80000000u) ? (e ^ 0x80000000u) : ~e);
}

// packed f32x2 helpers (sm_100+)
__device__ __forceinline__ unsigned long long pk2(float x, float y) {
    unsigned long long r;
    asm("mov.b64 %0, {%1, %2};" : "=l"(r) : "f"(x), "f"(y));
    return r;
}
__device__ __forceinline__ unsigned long long dup2(float x) {
    unsigned long long r;
    asm("mov.b64 %0, {%1, %1};" : "=l"(r) : "f"(x));
    return r;
}
__device__ __forceinline__ float2 upk(unsigned long long v) {
    float2 r;
    asm("mov.b64 {%0, %1}, %2;" : "=f"(r.x), "=f"(r.y) : "l"(v));
    return r;
}
__device__ __forceinline__ void ffma2(unsigned long long& d,
                                      unsigned long long a, unsigned long long b) {
    asm("fma.rn.f32x2 %0, %1, %2, %0;" : "+l"(d) : "l"(a), "l"(b));
}

// ---------------- prep: norms, biases, max init ----------------
__global__ void prep_kernel(const float* __restrict__ pos,
                            const float* __restrict__ lw,
                            const float* __restrict__ tpos)
{
    int i = blockIdx.x * blockDim.x + threadIdx.x;
    if (i >= NB * NL) return;
    const float* p = pos  + (size_t)i * ND;
    const float* t = tpos + (size_t)i * ND;
    float sp = 0.f, st = 0.f;
#pragma unroll
    for (int d = 0; d < ND; d++) { sp += p[d] * p[d]; st += t[d] * t[d]; }
    d_rbA[i] = -0.5f * sp;
    d_cbA[i] = lw[i] - 0.5f * sp;
    d_rbC[i] = -0.5f * st;
    d_mA[i] = 0u;   // below every valid encoding
    d_mC[i] = 0u;
}

// ---------------- dense score pass: P = X.Y^T + rowbias + colbias, with row max ----------------
// 128x128 tile per block, 8x8 per thread, packed f32x2 FFMA, K staged in 2 halves of 32.
#define SPAD 132
template <int PHASE>
__global__ __launch_bounds__(256, 2) void score_kernel(const float* __restrict__ X,
                                                       const float* __restrict__ Y)
{
    __shared__ float XsT[32][SPAD];   // transposed: [d][row]
    __shared__ float YsT[32][SPAD];   // transposed: [d][col]
    __shared__ unsigned rowm[128];

    const int b  = blockIdx.z;
    const int rt = blockIdx.y * 128;
    const int ct = blockIdx.x * 128;
    const int tid = threadIdx.x;
    const int tx = tid & 15;
    const int ty = tid >> 4;

    const float* Xb = X + ((size_t)b * NL + rt) * ND;
    const float* Yb = Y + ((size_t)b * NL + ct) * ND;

    if (tid < 128) rowm[tid] = 0u;

    unsigned long long acc2[8][4];
#pragma unroll
    for (int i = 0; i < 8; i++)
#pragma unroll
        for (int jp = 0; jp < 4; jp++) acc2[i][jp] = 0ull;

#pragma unroll
    for (int ks = 0; ks < 64; ks += 32) {
        __syncthreads();
        for (int i = tid; i < 128 * 8; i += 256) {
            int r  = i >> 3;
            int dv = (i & 7) * 4;
            float4 vx = *reinterpret_cast<const float4*>(&Xb[(size_t)r * ND + ks + dv]);
            XsT[dv + 0][r] = vx.x; XsT[dv + 1][r] = vx.y;
            XsT[dv + 2][r] = vx.z; XsT[dv + 3][r] = vx.w;
            float4 vy = *reinterpret_cast<const float4*>(&Yb[(size_t)r * ND + ks + dv]);
            YsT[dv + 0][r] = vy.x; YsT[dv + 1][r] = vy.y;
            YsT[dv + 2][r] = vy.z; YsT[dv + 3][r] = vy.w;
        }
        __syncthreads();

#pragma unroll 8
        for (int d = 0; d < 32; d++) {
            float4 x0 = *reinterpret_cast<const float4*>(&XsT[d][ty * 8]);
            float4 x1 = *reinterpret_cast<const float4*>(&XsT[d][ty * 8 + 4]);
            float4 y0 = *reinterpret_cast<const float4*>(&YsT[d][tx * 8]);
            float4 y1 = *reinterpret_cast<const float4*>(&YsT[d][tx * 8 + 4]);
            unsigned long long b2[4];
            b2[0] = pk2(y0.x, y0.y); b2[1] = pk2(y0.z, y0.w);
            b2[2] = pk2(y1.x, y1.y); b2[3] = pk2(y1.z, y1.w);
            unsigned long long a2[8];
            a2[0] = dup2(x0.x); a2[1] = dup2(x0.y); a2[2] = dup2(x0.z); a2[3] = dup2(x0.w);
            a2[4] = dup2(x1.x); a2[5] = dup2(x1.y); a2[6] = dup2(x1.z); a2[7] = dup2(x1.w);
#pragma unroll
            for (int i = 0; i < 8; i++)
#pragma unroll
                for (int jp = 0; jp < 4; jp++) ffma2(acc2[i][jp], a2[i], b2[jp]);
        }
    }

    const float* rb  = (PHASE == 0) ? d_rbA : d_rbC;
    const float* cb  = (PHASE == 0) ? d_cbA : d_cbC;
    unsigned*    men = (PHASE == 0) ? d_mA  : d_mC;

    float cbv[8];
#pragma unroll
    for (int j = 0; j < 8; j++) cbv[j] = cb[b * NL + ct + tx * 8 + j];

#pragma unroll
    for (int i = 0; i < 8; i++) {
        int r = rt + ty * 8 + i;
        float rbv = rb[b * NL + r];
        float v[8];
#pragma unroll
        for (int jp = 0; jp < 4; jp++) {
            float2 p = upk(acc2[i][jp]);
            v[2 * jp]     = p.x + rbv + cbv[2 * jp];
            v[2 * jp + 1] = p.y + rbv + cbv[2 * jp + 1];
        }
        float4 s0 = make_float4(v[0], v[1], v[2], v[3]);
        float4 s1 = make_float4(v[4], v[5], v[6], v[7]);
        float* Pr = &d_P[((size_t)b * NL + r) * NL + ct + tx * 8];
        *reinterpret_cast<float4*>(Pr)     = s0;
        *reinterpret_cast<float4*>(Pr + 4) = s1;
        float rm = fmaxf(fmaxf(fmaxf(v[0], v[1]), fmaxf(v[2], v[3])),
                         fmaxf(fmaxf(v[4], v[5]), fmaxf(v[6], v[7])));
#pragma unroll
        for (int off = 8; off > 0; off >>= 1)
            rm = fmaxf(rm, __shfl_xor_sync(0xFFFFFFFFu, rm, off));
        if (tx == 0) atomicMax(&rowm[ty * 8 + i], fenc(rm));
    }
    __syncthreads();
    if (tid < 128) atomicMax(&men[b * NL + rt + tid], rowm[tid]);
}

// ---------------- sparse build: warp per row, deterministic ordered compaction ----------------
// writes TRANSPOSED lists: entry j of row r at [(b*SCAP + j)*NL + r]
__global__ __launch_bounds__(256) void sparse_build_kernel()
{
    int gtid = blockIdx.x * blockDim.x + threadIdx.x;
    int w    = gtid >> 5;       // row index (b*NL + l)
    int lane = gtid & 31;
    if (w >= NB * NL) return;
    const int b = w >> 11;      // w / NL
    const int r = w & (NL - 1);
    const float* Pr = d_P + (size_t)w * NL;
    float m = fdec(d_mA[w]);
    float thr = m - STHRESH;
    int base = 0;
    for (int k0 = 0; k0 < NL; k0 += 32) {
        float p = Pr[k0 + lane];
        bool keep = (p > thr);
        unsigned mask = __ballot_sync(0xFFFFFFFFu, keep);
        if (keep) {
            int pos = base + __popc(mask & ((1u << lane) - 1u));
            if (pos < SCAP) {
                size_t idx = ((size_t)b * SCAP + pos) * NL + r;
                d_svalT[idx] = __expf(p - m);
                d_scolT[idx] = (unsigned short)(k0 + lane);
            }
        }
        base += __popc(mask);
    }
    if (lane == 0) d_scnt[w] = (base < SCAP) ? base : SCAP;
}

// ---------------- iterations: one block per batch, lists register-resident ----------------
__global__ __launch_bounds__(512, 1) void iterate_kernel(const float* __restrict__ lw)
{
    const int b   = blockIdx.x;
    const int tid = threadIdx.x;        // 512 threads, 4 rows each
    __shared__ float us[NL];            // exp(f)
    __shared__ unsigned conv;

    if (tid == 0) conv = 0u;

    float f[4], mrow[4];
    int   n[4];
    float vreg[4][RMAX];
    int   creg[4][RMAX];                // col * 4 (smem byte offset into us)

#pragma unroll
    for (int q = 0; q < 4; q++) {
        int r = tid + q * 512;
        f[q]    = 0.f;
        mrow[q] = fdec(d_mA[b * NL + r]);
        n[q]    = d_scnt[b * NL + r];
        // coalesced preload: entry j for consecutive rows is contiguous
#pragma unroll
        for (int j = 0; j < RMAX; j++) {
            size_t idx = ((size_t)b * SCAP + j) * NL + r;
            bool ok = (j < n[q]);
            vreg[q][j] = ok ? d_svalT[idx] : 0.f;
            creg[q][j] = ok ? ((int)d_scolT[idx] << 2) : 0;
        }
    }
    __syncthreads();

    for (int it = 0; it < NITER; it++) {
#pragma unroll
        for (int q = 0; q < 4; q++) us[tid + q * 512] = __expf(f[q]);
        __syncthreads();

        float s[4];
#pragma unroll
        for (int q = 0; q < 4; q++) {
            float acc = 0.f;
#pragma unroll
            for (int j = 0; j < RMAX; j++) {
                float u;
                asm volatile("ld.shared.f32 %0, [%1];"
                             : "=f"(u) : "r"((unsigned)__cvta_generic_to_shared(us) + (unsigned)creg[q][j]));
                acc = fmaf(vreg[q][j], u, acc);
            }
            // rare tail (n > RMAX), streamed from the coalesced transposed layout
            for (int j = RMAX; j < n[q]; j++) {
                size_t idx = ((size_t)b * SCAP + j) * NL + (tid + q * 512);
                acc = fmaf(d_svalT[idx], us[d_scolT[idx]], acc);
            }
            s[q] = acc;
        }

        float dmax = 0.f;
        float fn[4];
#pragma unroll
        for (int q = 0; q < 4; q++) {
            fn[q] = 0.5f * (f[q] - mrow[q] - __logf(s[q]));
            dmax = fmaxf(dmax, fabsf(fn[q] - f[q]));
        }
        __syncthreads();   // all us reads done before next overwrite
#pragma unroll
        for (int q = 0; q < 4; q++) f[q] = fn[q];

        if ((it & 7) == 7 && it < NITER - 1) {
            // deterministic convergence check: fixed point is stable, extra
            // iterations past |df|<2e-7 change the result by < 1e-6 absolute.
#pragma unroll
            for (int off = 16; off > 0; off >>= 1)
                dmax = fmaxf(dmax, __shfl_xor_sync(0xFFFFFFFFu, dmax, off));
            if ((tid & 31) == 0) atomicMax(&conv, fenc(dmax));
            __syncthreads();
            bool stop = fdec(conv) < 2e-7f;
            __syncthreads();
            if (tid == 0) conv = 0u;
            if (stop) break;
        }
    }

    // column bias for the cross pass: lw_l + f_l - 0.5*||pos_l||^2
#pragma unroll
    for (int q = 0; q < 4; q++) {
        int r = tid + q * 512;
        d_cbC[b * NL + r] = lw[b * NL + r] + f[q] + d_rbA[b * NL + r];
    }
}

// ---------------- cross LSE: block per target row (max precomputed by score<1>) ----------------
__global__ __launch_bounds__(256) void lse_cross_kernel(const float* __restrict__ tlw)
{
    const int row = blockIdx.x;              // b*NL + t
    const float4* Sr4 = reinterpret_cast<const float4*>(d_P + (size_t)row * NL);
    float m = fdec(d_mC[row]);
    float s = 0.f;
    for (int k = threadIdx.x; k < NL / 4; k += 256) {
        float4 v = Sr4[k];
        s += __expf(v.x - m) + __expf(v.y - m) + __expf(v.z - m) + __expf(v.w - m);
    }
    __shared__ float red[256];
    red[threadIdx.x] = s;
    __syncthreads();
    for (int off = 128; off > 0; off >>= 1) {
        if (threadIdx.x < off) red[threadIdx.x] += red[threadIdx.x + off];
        __syncthreads();
    }
    if (threadIdx.x == 0) {
        float g = -(m + __logf(red[0]));
        d_gw[row] = g * __expf(tlw[row]);
    }
}

// ---------------- deterministic final reduction ----------------
__global__ __launch_bounds__(256) void reduce_kernel(float* __restrict__ out)
{
    const int b = blockIdx.x;
    float s = 0.f;
    for (int k = threadIdx.x; k < NL; k += 256) s += d_gw[b * NL + k];
    __shared__ float red[256];
    red[threadIdx.x] = s;
    __syncthreads();
    for (int off = 128; off > 0; off >>= 1) {
        if (threadIdx.x < off) red[threadIdx.x] += red[threadIdx.x + off];
        __syncthreads();
    }
    if (threadIdx.x == 0) out[b] = red[0];
}

// ---------------- launch ----------------
extern "C" void kernel_launch(void* const* d_in, const int* in_sizes, int n_in,
                              void* d_out, int out_size)
{
    const float* pos  = (const float*)d_in[0];   // (8, 2048, 64)
    const float* lw   = (const float*)d_in[1];   // (8, 2048)
    const float* tpos = (const float*)d_in[2];   // (8, 2048, 64)
    const float* tlw  = (const float*)d_in[3];   // (8, 2048)
    float* out = (float*)d_out;                  // (8,)

    prep_kernel<<<(NB * NL + 255) / 256, 256>>>(pos, lw, tpos);

    dim3 g(NL / 128, NL / 128, NB);
    score_kernel<0><<<g, 256>>>(pos, pos);

    sparse_build_kernel<<<(NB * NL * 32) / 256, 256>>>();

    iterate_kernel<<<NB, 512>>>(lw);

    score_kernel<1><<<g, 256>>>(tpos, pos);

    lse_cross_kernel<<<NB * NL, 256>>>(tlw);

    reduce_kernel<<<NB, 256>>>(out);
}

// round 11
// speedup vs baseline: 5.0203x; 5.0203x over previous
#include <cuda_runtime.h>
#include <cstdint>

#define NB 8
#define NL 2048
#define ND 64
#define SCAP 256
#define STHRESH 35.0f
#define NITER 100
#define RMAX 12           // register-resident entries per row in iterate

// ---------------- static device scratch (no runtime allocation) ----------------
static __device__ float    d_P[(size_t)NB * NL * NL];   // dense scores (134 MB), reused self & cross
static __device__ unsigned d_mA[NB * NL];               // encoded row max (self)
static __device__ unsigned d_mC[NB * NL];               // encoded row max (cross)
static __device__ float    d_rbA[NB * NL];              // -0.5*||pos||^2
static __device__ float    d_cbA[NB * NL];              // lw - 0.5*||pos||^2
static __device__ float    d_rbC[NB * NL];              // -0.5*||tpos||^2
static __device__ float    d_cbC[NB * NL];              // lw + f - 0.5*||pos||^2 (after iterate)
static __device__ int      d_scnt[NB * NL];             // nnz per row
// transposed sparse lists: entry j of row r at [(b*SCAP + j)*NL + r]  (coalesced across rows)
static __device__ float          d_svalT[(size_t)NB * SCAP * NL];
static __device__ unsigned short d_scolT[(size_t)NB * SCAP * NL];
static __device__ float    d_gw[NB * NL];               // g * exp(tlw) partials

// monotone float<->uint encoding for atomicMax on floats (any sign)
__device__ __forceinline__ unsigned fenc(float f) {
    unsigned u = __float_as_uint(f);
    return (u & 0x80000000u) ? ~u : (u | 0x80000000u);
}
__device__ __forceinline__ float fdec(unsigned e) {
    return __uint_as_float((e & 0x80000000u) ? (e ^ 0x80000000u) : ~e);
}

// packed f32x2 helpers (sm_100+)
__device__ __forceinline__ unsigned long long pk2(float x, float y) {
    unsigned long long r;
    asm("mov.b64 %0, {%1, %2};" : "=l"(r) : "f"(x), "f"(y));
    return r;
}
__device__ __forceinline__ unsigned long long dup2(float x) {
    unsigned long long r;
    asm("mov.b64 %0, {%1, %1};" : "=l"(r) : "f"(x));
    return r;
}
__device__ __forceinline__ float2 upk(unsigned long long v) {
    float2 r;
    asm("mov.b64 {%0, %1}, %2;" : "=f"(r.x), "=f"(r.y) : "l"(v));
    return r;
}
__device__ __forceinline__ void ffma2(unsigned long long& d,
                                      unsigned long long a, unsigned long long b) {
    asm("fma.rn.f32x2 %0, %1, %2, %0;" : "+l"(d) : "l"(a), "l"(b));
}

// ---------------- prep: norms, biases, max init ----------------
__global__ void prep_kernel(const float* __restrict__ pos,
                            const float* __restrict__ lw,
                            const float* __restrict__ tpos)
{
    int i = blockIdx.x * blockDim.x + threadIdx.x;
    if (i >= NB * NL) return;
    const float* p = pos  + (size_t)i * ND;
    const float* t = tpos + (size_t)i * ND;
    float sp = 0.f, st = 0.f;
#pragma unroll
    for (int d = 0; d < ND; d++) { sp += p[d] * p[d]; st += t[d] * t[d]; }
    d_rbA[i] = -0.5f * sp;
    d_cbA[i] = lw[i] - 0.5f * sp;
    d_rbC[i] = -0.5f * st;
    d_mA[i] = 0u;   // below every valid encoding
    d_mC[i] = 0u;
}

// ---------------- dense score pass: P = X.Y^T + rowbias + colbias, with row max ----------------
// 128x128 tile per block, 8x8 per thread, packed f32x2 FFMA, K staged in 2 halves of 32.
#define SPAD 132
template <int PHASE>
__global__ __launch_bounds__(256, 2) void score_kernel(const float* __restrict__ X,
                                                       const float* __restrict__ Y)
{
    __shared__ float XsT[32][SPAD];   // transposed: [d][row]
    __shared__ float YsT[32][SPAD];   // transposed: [d][col]
    __shared__ unsigned rowm[128];

    const int b  = blockIdx.z;
    const int rt = blockIdx.y * 128;
    const int ct = blockIdx.x * 128;
    const int tid = threadIdx.x;
    const int tx = tid & 15;
    const int ty = tid >> 4;

    const float* Xb = X + ((size_t)b * NL + rt) * ND;
    const float* Yb = Y + ((size_t)b * NL + ct) * ND;

    if (tid < 128) rowm[tid] = 0u;

    unsigned long long acc2[8][4];
#pragma unroll
    for (int i = 0; i < 8; i++)
#pragma unroll
        for (int jp = 0; jp < 4; jp++) acc2[i][jp] = 0ull;

#pragma unroll
    for (int ks = 0; ks < 64; ks += 32) {
        __syncthreads();
        for (int i = tid; i < 128 * 8; i += 256) {
            int r  = i >> 3;
            int dv = (i & 7) * 4;
            float4 vx = *reinterpret_cast<const float4*>(&Xb[(size_t)r * ND + ks + dv]);
            XsT[dv + 0][r] = vx.x; XsT[dv + 1][r] = vx.y;
            XsT[dv + 2][r] = vx.z; XsT[dv + 3][r] = vx.w;
            float4 vy = *reinterpret_cast<const float4*>(&Yb[(size_t)r * ND + ks + dv]);
            YsT[dv + 0][r] = vy.x; YsT[dv + 1][r] = vy.y;
            YsT[dv + 2][r] = vy.z; YsT[dv + 3][r] = vy.w;
        }
        __syncthreads();

#pragma unroll 8
        for (int d = 0; d < 32; d++) {
            float4 x0 = *reinterpret_cast<const float4*>(&XsT[d][ty * 8]);
            float4 x1 = *reinterpret_cast<const float4*>(&XsT[d][ty * 8 + 4]);
            float4 y0 = *reinterpret_cast<const float4*>(&YsT[d][tx * 8]);
            float4 y1 = *reinterpret_cast<const float4*>(&YsT[d][tx * 8 + 4]);
            unsigned long long b2[4];
            b2[0] = pk2(y0.x, y0.y); b2[1] = pk2(y0.z, y0.w);
            b2[2] = pk2(y1.x, y1.y); b2[3] = pk2(y1.z, y1.w);
            unsigned long long a2[8];
            a2[0] = dup2(x0.x); a2[1] = dup2(x0.y); a2[2] = dup2(x0.z); a2[3] = dup2(x0.w);
            a2[4] = dup2(x1.x); a2[5] = dup2(x1.y); a2[6] = dup2(x1.z); a2[7] = dup2(x1.w);
#pragma unroll
            for (int i = 0; i < 8; i++)
#pragma unroll
                for (int jp = 0; jp < 4; jp++) ffma2(acc2[i][jp], a2[i], b2[jp]);
        }
    }

    const float* rb  = (PHASE == 0) ? d_rbA : d_rbC;
    const float* cb  = (PHASE == 0) ? d_cbA : d_cbC;
    unsigned*    men = (PHASE == 0) ? d_mA  : d_mC;

    float cbv[8];
#pragma unroll
    for (int j = 0; j < 8; j++) cbv[j] = cb[b * NL + ct + tx * 8 + j];

#pragma unroll
    for (int i = 0; i < 8; i++) {
        int r = rt + ty * 8 + i;
        float rbv = rb[b * NL + r];
        float v[8];
#pragma unroll
        for (int jp = 0; jp < 4; jp++) {
            float2 p = upk(acc2[i][jp]);
            v[2 * jp]     = p.x + rbv + cbv[2 * jp];
            v[2 * jp + 1] = p.y + rbv + cbv[2 * jp + 1];
        }
        float4 s0 = make_float4(v[0], v[1], v[2], v[3]);
        float4 s1 = make_float4(v[4], v[5], v[6], v[7]);
        float* Pr = &d_P[((size_t)b * NL + r) * NL + ct + tx * 8];
        *reinterpret_cast<float4*>(Pr)     = s0;
        *reinterpret_cast<float4*>(Pr + 4) = s1;
        float rm = fmaxf(fmaxf(fmaxf(v[0], v[1]), fmaxf(v[2], v[3])),
                         fmaxf(fmaxf(v[4], v[5]), fmaxf(v[6], v[7])));
#pragma unroll
        for (int off = 8; off > 0; off >>= 1)
            rm = fmaxf(rm, __shfl_xor_sync(0xFFFFFFFFu, rm, off));
        if (tx == 0) atomicMax(&rowm[ty * 8 + i], fenc(rm));
    }
    __syncthreads();
    if (tid < 128) atomicMax(&men[b * NL + rt + tid], rowm[tid]);
}

// ---------------- sparse build: warp per row, deterministic ordered compaction ----------------
// writes TRANSPOSED lists: entry j of row r at [(b*SCAP + j)*NL + r]
__global__ __launch_bounds__(256) void sparse_build_kernel()
{
    int gtid = blockIdx.x * blockDim.x + threadIdx.x;
    int w    = gtid >> 5;       // row index (b*NL + l)
    int lane = gtid & 31;
    if (w >= NB * NL) return;
    const int b = w >> 11;      // w / NL
    const int r = w & (NL - 1);
    const float* Pr = d_P + (size_t)w * NL;
    float m = fdec(d_mA[w]);
    float thr = m - STHRESH;
    int base = 0;
    for (int k0 = 0; k0 < NL; k0 += 32) {
        float p = Pr[k0 + lane];
        bool keep = (p > thr);
        unsigned mask = __ballot_sync(0xFFFFFFFFu, keep);
        if (keep) {
            int pos = base + __popc(mask & ((1u << lane) - 1u));
            if (pos < SCAP) {
                size_t idx = ((size_t)b * SCAP + pos) * NL + r;
                d_svalT[idx] = __expf(p - m);
                d_scolT[idx] = (unsigned short)(k0 + lane);
            }
        }
        base += __popc(mask);
    }
    if (lane == 0) d_scnt[w] = (base < SCAP) ? base : SCAP;
}

// ---------------- iterations: one block per batch, lists truly register-resident ----------------
// 1024 threads, 2 rows each. 24 fp32 vals + 12 packed-u16x2 col ints per thread
// (~55 regs total, no spill under __launch_bounds__(1024,1)).
__global__ __launch_bounds__(1024, 1) void iterate_kernel(const float* __restrict__ lw)
{
    const int b   = blockIdx.x;
    const int tid = threadIdx.x;
    __shared__ float us[NL];            // exp(f)
    __shared__ unsigned conv;

    if (tid == 0) conv = 0u;

    const int r0 = tid, r1 = tid + 1024;
    const float m0 = fdec(d_mA[b * NL + r0]);
    const float m1 = fdec(d_mA[b * NL + r1]);
    const int   n0 = d_scnt[b * NL + r0];
    const int   n1 = d_scnt[b * NL + r1];

    float v0[RMAX], v1[RMAX];
    int   cp0[RMAX / 2], cp1[RMAX / 2];   // two u16 element-indices per int

    {
        int ctmp0[RMAX], ctmp1[RMAX];
#pragma unroll
        for (int j = 0; j < RMAX; j++) {
            size_t i0 = ((size_t)b * SCAP + j) * NL + r0;   // coalesced across tid
            size_t i1 = ((size_t)b * SCAP + j) * NL + r1;
            bool k0 = (j < n0), k1 = (j < n1);
            v0[j]    = k0 ? d_svalT[i0] : 0.f;
            ctmp0[j] = k0 ? (int)d_scolT[i0] : 0;
            v1[j]    = k1 ? d_svalT[i1] : 0.f;
            ctmp1[j] = k1 ? (int)d_scolT[i1] : 0;
        }
#pragma unroll
        for (int h = 0; h < RMAX / 2; h++) {
            cp0[h] = ctmp0[2 * h] | (ctmp0[2 * h + 1] << 16);
            cp1[h] = ctmp1[2 * h] | (ctmp1[2 * h + 1] << 16);
        }
    }

    float f0 = 0.f, f1 = 0.f;
    __syncthreads();

    for (int it = 0; it < NITER; it++) {
        us[r0] = __expf(f0);
        us[r1] = __expf(f1);
        __syncthreads();

        float s0 = 0.f, s1 = 0.f;
#pragma unroll
        for (int h = 0; h < RMAX / 2; h++) {
            int p0 = cp0[h], p1 = cp1[h];
            s0 = fmaf(v0[2 * h],     us[p0 & 0xFFFF], s0);
            s0 = fmaf(v0[2 * h + 1], us[p0 >> 16],    s0);
            s1 = fmaf(v1[2 * h],     us[p1 & 0xFFFF], s1);
            s1 = fmaf(v1[2 * h + 1], us[p1 >> 16],    s1);
        }
        // rare tail (nnz > RMAX): coalesced, L1-resident after first iteration
        for (int j = RMAX; j < n0; j++) {
            size_t idx = ((size_t)b * SCAP + j) * NL + r0;
            s0 = fmaf(d_svalT[idx], us[d_scolT[idx]], s0);
        }
        for (int j = RMAX; j < n1; j++) {
            size_t idx = ((size_t)b * SCAP + j) * NL + r1;
            s1 = fmaf(d_svalT[idx], us[d_scolT[idx]], s1);
        }

        float fn0 = 0.5f * (f0 - m0 - __logf(s0));
        float fn1 = 0.5f * (f1 - m1 - __logf(s1));
        float dmax = fmaxf(fabsf(fn0 - f0), fabsf(fn1 - f1));
        __syncthreads();   // all us reads done before next overwrite
        f0 = fn0;
        f1 = fn1;

        if ((it & 3) == 3 && it < NITER - 1) {
            // deterministic convergence exit: remaining drift <= 2*dmax < 2e-6 abs
#pragma unroll
            for (int off = 16; off > 0; off >>= 1)
                dmax = fmaxf(dmax, __shfl_xor_sync(0xFFFFFFFFu, dmax, off));
            if ((tid & 31) == 0) atomicMax(&conv, fenc(dmax));
            __syncthreads();
            bool stop = fdec(conv) < 1e-6f;
            __syncthreads();
            if (tid == 0) conv = 0u;
            if (stop) break;
        }
    }

    // column bias for the cross pass: lw_l + f_l - 0.5*||pos_l||^2
    d_cbC[b * NL + r0] = lw[b * NL + r0] + f0 + d_rbA[b * NL + r0];
    d_cbC[b * NL + r1] = lw[b * NL + r1] + f1 + d_rbA[b * NL + r1];
}

// ---------------- cross LSE: block per target row (max precomputed by score<1>) ----------------
__global__ __launch_bounds__(256) void lse_cross_kernel(const float* __restrict__ tlw)
{
    const int row = blockIdx.x;              // b*NL + t
    const float4* Sr4 = reinterpret_cast<const float4*>(d_P + (size_t)row * NL);
    float m = fdec(d_mC[row]);
    float s = 0.f;
    for (int k = threadIdx.x; k < NL / 4; k += 256) {
        float4 v = Sr4[k];
        s += __expf(v.x - m) + __expf(v.y - m) + __expf(v.z - m) + __expf(v.w - m);
    }
    __shared__ float red[256];
    red[threadIdx.x] = s;
    __syncthreads();
    for (int off = 128; off > 0; off >>= 1) {
        if (threadIdx.x < off) red[threadIdx.x] += red[threadIdx.x + off];
        __syncthreads();
    }
    if (threadIdx.x == 0) {
        float g = -(m + __logf(red[0]));
        d_gw[row] = g * __expf(tlw[row]);
    }
}

// ---------------- deterministic final reduction ----------------
__global__ __launch_bounds__(256) void reduce_kernel(float* __restrict__ out)
{
    const int b = blockIdx.x;
    float s = 0.f;
    for (int k = threadIdx.x; k < NL; k += 256) s += d_gw[b * NL + k];
    __shared__ float red[256];
    red[threadIdx.x] = s;
    __syncthreads();
    for (int off = 128; off > 0; off >>= 1) {
        if (threadIdx.x < off) red[threadIdx.x] += red[threadIdx.x + off];
        __syncthreads();
    }
    if (threadIdx.x == 0) out[b] = red[0];
}

// ---------------- launch ----------------
extern "C" void kernel_launch(void* const* d_in, const int* in_sizes, int n_in,
                              void* d_out, int out_size)
{
    const float* pos  = (const float*)d_in[0];   // (8, 2048, 64)
    const float* lw   = (const float*)d_in[1];   // (8, 2048)
    const float* tpos = (const float*)d_in[2];   // (8, 2048, 64)
    const float* tlw  = (const float*)d_in[3];   // (8, 2048)
    float* out = (float*)d_out;                  // (8,)

    prep_kernel<<<(NB * NL + 255) / 256, 256>>>(pos, lw, tpos);

    dim3 g(NL / 128, NL / 128, NB);
    score_kernel<0><<<g, 256>>>(pos, pos);

    sparse_build_kernel<<<(NB * NL * 32) / 256, 256>>>();

    iterate_kernel<<<NB, 1024>>>(lw);

    score_kernel<1><<<g, 256>>>(tpos, pos);

    lse_cross_kernel<<<NB * NL, 256>>>(tlw);

    reduce_kernel<<<NB, 256>>>(out);
}

// round 13
// speedup vs baseline: 6.4730x; 1.2894x over previous
#include <cuda_runtime.h>
#include <cstdint>

#define NB 8
#define NL 2048
#define ND 64
#define CAP2 40           // max sparse entries kept per row (diag always in slot 0)
#define STHRESH 35.0f
#define NITER 100
#define RMAX 12           // register-resident entries per row in iterate
#define SPAD2 132

// ---------------- static device scratch (no runtime allocation) ----------------
static __device__ float    d_rbA[NB * NL];              // -0.5*||pos||^2
static __device__ float    d_cbA[NB * NL];              // lw - 0.5*||pos||^2
static __device__ float    d_rbC[NB * NL];              // -0.5*||tpos||^2
static __device__ float    d_cbC[NB * NL];              // lw + f - 0.5*||pos||^2 (after iterate)
static __device__ int      d_scnt[NB * NL];             // nnz per row (<= CAP2)
// transposed sparse lists: entry j of row r at [(b*CAP2 + j)*NL + r]  (coalesced across rows)
static __device__ float          d_svalT[(size_t)NB * CAP2 * NL];
static __device__ unsigned short d_scolT[(size_t)NB * CAP2 * NL];
static __device__ unsigned d_MbEnc[NB];                 // encoded per-batch shift max(lw+f)
static __device__ float    d_gw[NB * NL];               // g * exp(tlw) partials

// monotone float<->uint encoding for atomicMax on floats (any sign)
__device__ __forceinline__ unsigned fenc(float f) {
    unsigned u = __float_as_uint(f);
    return (u & 0x80000000u) ? ~u : (u | 0x80000000u);
}
__device__ __forceinline__ float fdec(unsigned e) {
    return __uint_as_float((e & 0x80000000u) ? (e ^ 0x80000000u) : ~e);
}

// packed f32x2 helpers (sm_100+)
__device__ __forceinline__ unsigned long long pk2(float x, float y) {
    unsigned long long r;
    asm("mov.b64 %0, {%1, %2};" : "=l"(r) : "f"(x), "f"(y));
    return r;
}
__device__ __forceinline__ unsigned long long dup2(float x) {
    unsigned long long r;
    asm("mov.b64 %0, {%1, %1};" : "=l"(r) : "f"(x));
    return r;
}
__device__ __forceinline__ float2 upk(unsigned long long v) {
    float2 r;
    asm("mov.b64 {%0, %1}, %2;" : "=f"(r.x), "=f"(r.y) : "l"(v));
    return r;
}
__device__ __forceinline__ void ffma2(unsigned long long& d,
                                      unsigned long long a, unsigned long long b) {
    asm("fma.rn.f32x2 %0, %1, %2, %0;" : "+l"(d) : "l"(a), "l"(b));
}

// ---------------- prep: norms, biases ----------------
__global__ void prep_kernel(const float* __restrict__ pos,
                            const float* __restrict__ lw,
                            const float* __restrict__ tpos)
{
    int i = blockIdx.x * blockDim.x + threadIdx.x;
    if (i >= NB * NL) return;
    const float* p = pos  + (size_t)i * ND;
    const float* t = tpos + (size_t)i * ND;
    float sp = 0.f, st = 0.f;
#pragma unroll
    for (int d = 0; d < ND; d++) { sp += p[d] * p[d]; st += t[d] * t[d]; }
    d_rbA[i] = -0.5f * sp;
    d_cbA[i] = lw[i] - 0.5f * sp;
    d_rbC[i] = -0.5f * st;
}

// ---------------- fused score pass: 128-row stripe per block, loops 16 col tiles ----------------
// PHASE 0 (self): threshold vs (lw_r - STHRESH), shift m = lw_r (row max == lw_r + O(lw spread),
//   spread << STHRESH), emit sparse lists inline. Diagonal (col==row) forced into slot 0 so
//   capacity truncation can never drop the dominant term. No dense matrix ever written.
// PHASE 1 (cross): accumulate per-row sum of exp(P - Mb) across tiles, write d_gw directly.
template <int PHASE>
__global__ __launch_bounds__(256, 1) void score_fused(const float* __restrict__ X,
                                                      const float* __restrict__ Y,
                                                      const float* __restrict__ W)   // lw (P0) / tlw (P1)
{
    __shared__ float XsT[16][SPAD2];          // transposed stage: [d][row]
    __shared__ float YsT[16][SPAD2];          // transposed stage: [d][col]
    __shared__ float          s_val[128][CAP2 + 1]; // per-row sparse staging (PHASE 0)
    __shared__ unsigned short s_col[128][CAP2 + 1];
    __shared__ int   s_cnt[128];

    const int b   = blockIdx.y;
    const int rt  = blockIdx.x * 128;
    const int tid = threadIdx.x;
    const int tx  = tid & 15;
    const int ty  = tid >> 4;
    const int lane = tid & 31;
    const int txl  = lane & 15;

    const float* rb = PHASE ? d_rbC : d_rbA;
    const float* cb = PHASE ? d_cbC : d_cbA;

    float rbr[8], lwr[8];
#pragma unroll
    for (int i = 0; i < 8; i++) {
        int row = rt + ty * 8 + i;
        rbr[i] = rb[b * NL + row];
        if (PHASE == 0) lwr[i] = W[b * NL + row];
    }
    float Mb = 0.f;
    if (PHASE == 1) Mb = fdec(d_MbEnc[b]);

    int   base[8];     // count of kept NON-diagonal entries (diag lives in slot 0)
    float sv[8];
#pragma unroll
    for (int i = 0; i < 8; i++) { base[i] = 0; sv[i] = 0.f; }

    const float* Xb = X + ((size_t)b * NL + rt) * ND;

    for (int ct = 0; ct < NL; ct += 128) {
        const float* Yb = Y + ((size_t)b * NL + ct) * ND;

        unsigned long long acc2[8][4];
#pragma unroll
        for (int i = 0; i < 8; i++)
#pragma unroll
            for (int jp = 0; jp < 4; jp++) acc2[i][jp] = 0ull;

#pragma unroll
        for (int ks = 0; ks < ND; ks += 16) {
            __syncthreads();
            for (int idx2 = tid; idx2 < 128 * 4; idx2 += 256) {
                int r  = idx2 >> 2;
                int dv = (idx2 & 3) * 4;
                float4 vx = *reinterpret_cast<const float4*>(&Xb[(size_t)r * ND + ks + dv]);
                XsT[dv + 0][r] = vx.x; XsT[dv + 1][r] = vx.y;
                XsT[dv + 2][r] = vx.z; XsT[dv + 3][r] = vx.w;
                float4 vy = *reinterpret_cast<const float4*>(&Yb[(size_t)r * ND + ks + dv]);
                YsT[dv + 0][r] = vy.x; YsT[dv + 1][r] = vy.y;
                YsT[dv + 2][r] = vy.z; YsT[dv + 3][r] = vy.w;
            }
            __syncthreads();

#pragma unroll
            for (int d = 0; d < 16; d++) {
                float4 x0 = *reinterpret_cast<const float4*>(&XsT[d][ty * 8]);
                float4 x1 = *reinterpret_cast<const float4*>(&XsT[d][ty * 8 + 4]);
                float4 y0 = *reinterpret_cast<const float4*>(&YsT[d][tx * 8]);
                float4 y1 = *reinterpret_cast<const float4*>(&YsT[d][tx * 8 + 4]);
                unsigned long long b2[4];
                b2[0] = pk2(y0.x, y0.y); b2[1] = pk2(y0.z, y0.w);
                b2[2] = pk2(y1.x, y1.y); b2[3] = pk2(y1.z, y1.w);
                unsigned long long a2[8];
                a2[0] = dup2(x0.x); a2[1] = dup2(x0.y); a2[2] = dup2(x0.z); a2[3] = dup2(x0.w);
                a2[4] = dup2(x1.x); a2[5] = dup2(x1.y); a2[6] = dup2(x1.z); a2[7] = dup2(x1.w);
#pragma unroll
                for (int i = 0; i < 8; i++)
#pragma unroll
                    for (int jp = 0; jp < 4; jp++) ffma2(acc2[i][jp], a2[i], b2[jp]);
            }
        }

        // -------- per-tile epilogue --------
        float cbv[8];
#pragma unroll
        for (int j = 0; j < 8; j++) cbv[j] = cb[b * NL + ct + tx * 8 + j];

#pragma unroll
        for (int i = 0; i < 8; i++) {
            float v[8];
#pragma unroll
            for (int jp = 0; jp < 4; jp++) {
                float2 p = upk(acc2[i][jp]);
                v[2 * jp]     = p.x + rbr[i] + cbv[2 * jp];
                v[2 * jp + 1] = p.y + rbr[i] + cbv[2 * jp + 1];
            }
            if (PHASE == 0) {
                float thr = lwr[i] - STHRESH;
                int grow = rt + ty * 8 + i;      // global row
                int rloc = ty * 8 + i;           // local row
#pragma unroll
                for (int j = 0; j < 8; j++) {
                    int gcol = ct + tx * 8 + j;
                    bool isd  = (gcol == grow);
                    bool keep = (v[j] > thr) && !isd;
                    unsigned bm  = __ballot_sync(0xFFFFFFFFu, keep);
                    unsigned grp = (lane < 16) ? (bm & 0xFFFFu) : (bm >> 16);
                    if (isd) {
                        // diagonal always kept, pinned to slot 0 (one thread per row)
                        s_val[rloc][0] = __expf(v[j] - lwr[i]);
                        s_col[rloc][0] = (unsigned short)gcol;
                    }
                    if (keep) {
                        int pos = 1 + base[i] + __popc(grp & ((1u << txl) - 1u));
                        if (pos < CAP2) {
                            s_val[rloc][pos] = __expf(v[j] - lwr[i]);
                            s_col[rloc][pos] = (unsigned short)gcol;
                        }
                    }
                    base[i] += __popc(grp);
                }
            } else {
                float e = __expf(v[0] - Mb) + __expf(v[1] - Mb)
                        + __expf(v[2] - Mb) + __expf(v[3] - Mb)
                        + __expf(v[4] - Mb) + __expf(v[5] - Mb)
                        + __expf(v[6] - Mb) + __expf(v[7] - Mb);
                sv[i] += e;
            }
        }
    }

    // -------- final epilogue --------
    if (PHASE == 0) {
        if (txl == 0) {
#pragma unroll
            for (int i = 0; i < 8; i++) {
                int c = 1 + base[i];             // diag + non-diag kept
                s_cnt[ty * 8 + i] = (c < CAP2) ? c : CAP2;
            }
        }
        __syncthreads();
        // coalesced transposed write of the lists (zeros beyond count)
        for (int idx = tid; idx < 128 * CAP2; idx += 256) {
            int j  = idx >> 7;       // slot (slow)
            int rr = idx & 127;      // row  (fast -> contiguous global)
            int c = s_cnt[rr];
            size_t o = ((size_t)b * CAP2 + j) * NL + rt + rr;
            d_svalT[o] = (j < c) ? s_val[rr][j] : 0.f;
            d_scolT[o] = (j < c) ? s_col[rr][j] : (unsigned short)0;
        }
        if (tid < 128) d_scnt[b * NL + rt + tid] = s_cnt[tid];
    } else {
#pragma unroll
        for (int i = 0; i < 8; i++) {
            float s = sv[i];
#pragma unroll
            for (int off = 8; off > 0; off >>= 1)
                s += __shfl_xor_sync(0xFFFFFFFFu, s, off);   // stays within 16-lane group
            if (txl == 0) {
                int row = rt + ty * 8 + i;
                float g = -(Mb + __logf(s));
                d_gw[b * NL + row] = g * __expf(W[b * NL + row]);
            }
        }
    }
}

// ---------------- iterations: one block per batch, lists register-resident ----------------
__global__ __launch_bounds__(1024, 1) void iterate_kernel(const float* __restrict__ lw)
{
    const int b   = blockIdx.x;
    const int tid = threadIdx.x;
    __shared__ float us[NL];            // exp(f)
    __shared__ unsigned conv;
    __shared__ unsigned mbred;

    if (tid == 0) { conv = 0u; mbred = 0u; }

    const int r0 = tid, r1 = tid + 1024;
    const float lw0 = lw[b * NL + r0];
    const float lw1 = lw[b * NL + r1];
    const float m0 = lw0, m1 = lw1;     // shift = lw_r (matches sparse-build shift)
    const int   n0 = d_scnt[b * NL + r0];
    const int   n1 = d_scnt[b * NL + r1];

    float v0[RMAX], v1[RMAX];
    int   cp0[RMAX / 2], cp1[RMAX / 2];   // two u16 element-indices per int

    {
        int ctmp0[RMAX], ctmp1[RMAX];
#pragma unroll
        for (int j = 0; j < RMAX; j++) {
            size_t i0 = ((size_t)b * CAP2 + j) * NL + r0;   // coalesced across tid
            size_t i1 = ((size_t)b * CAP2 + j) * NL + r1;
            bool k0 = (j < n0), k1 = (j < n1);
            v0[j]    = k0 ? d_svalT[i0] : 0.f;
            ctmp0[j] = k0 ? (int)d_scolT[i0] : 0;
            v1[j]    = k1 ? d_svalT[i1] : 0.f;
            ctmp1[j] = k1 ? (int)d_scolT[i1] : 0;
        }
#pragma unroll
        for (int h = 0; h < RMAX / 2; h++) {
            cp0[h] = ctmp0[2 * h] | (ctmp0[2 * h + 1] << 16);
            cp1[h] = ctmp1[2 * h] | (ctmp1[2 * h + 1] << 16);
        }
    }

    float f0 = 0.f, f1 = 0.f;
    __syncthreads();

    for (int it = 0; it < NITER; it++) {
        us[r0] = __expf(f0);
        us[r1] = __expf(f1);
        __syncthreads();

        float s0 = 0.f, s1 = 0.f;
#pragma unroll
        for (int h = 0; h < RMAX / 2; h++) {
            int p0 = cp0[h], p1 = cp1[h];
            s0 = fmaf(v0[2 * h],     us[p0 & 0xFFFF], s0);
            s0 = fmaf(v0[2 * h + 1], us[p0 >> 16],    s0);
            s1 = fmaf(v1[2 * h],     us[p1 & 0xFFFF], s1);
            s1 = fmaf(v1[2 * h + 1], us[p1 >> 16],    s1);
        }
        // rare tail (nnz > RMAX): coalesced, L1-resident after first iteration
        for (int j = RMAX; j < n0; j++) {
            size_t idx = ((size_t)b * CAP2 + j) * NL + r0;
            s0 = fmaf(d_svalT[idx], us[d_scolT[idx]], s0);
        }
        for (int j = RMAX; j < n1; j++) {
            size_t idx = ((size_t)b * CAP2 + j) * NL + r1;
            s1 = fmaf(d_svalT[idx], us[d_scolT[idx]], s1);
        }

        float fn0 = 0.5f * (f0 - m0 - __logf(s0));
        float fn1 = 0.5f * (f1 - m1 - __logf(s1));
        float dmax = fmaxf(fabsf(fn0 - f0), fabsf(fn1 - f1));
        __syncthreads();   // all us reads done before next overwrite
        f0 = fn0;
        f1 = fn1;

        if ((it & 3) == 3 && it < NITER - 1) {
            // deterministic convergence exit: remaining drift ~2*dmax < 2e-6 abs
#pragma unroll
            for (int off = 16; off > 0; off >>= 1)
                dmax = fmaxf(dmax, __shfl_xor_sync(0xFFFFFFFFu, dmax, off));
            if ((tid & 31) == 0) atomicMax(&conv, fenc(dmax));
            __syncthreads();
            bool stop = fdec(conv) < 1e-6f;
            __syncthreads();
            if (tid == 0) conv = 0u;
            if (stop) break;
        }
    }

    // per-batch shift for the cross pass: Mb = max_k(lw_k + f_k)  (order-independent max)
    float lf = fmaxf(lw0 + f0, lw1 + f1);
#pragma unroll
    for (int off = 16; off > 0; off >>= 1)
        lf = fmaxf(lf, __shfl_xor_sync(0xFFFFFFFFu, lf, off));
    if ((tid & 31) == 0) atomicMax(&mbred, fenc(lf));

    // column bias for the cross pass: lw_l + f_l - 0.5*||pos_l||^2
    d_cbC[b * NL + r0] = lw0 + f0 + d_rbA[b * NL + r0];
    d_cbC[b * NL + r1] = lw1 + f1 + d_rbA[b * NL + r1];

    __syncthreads();
    if (tid == 0) d_MbEnc[b] = mbred;
}

// ---------------- deterministic final reduction ----------------
__global__ __launch_bounds__(256) void reduce_kernel(float* __restrict__ out)
{
    const int b = blockIdx.x;
    float s = 0.f;
    for (int k = threadIdx.x; k < NL; k += 256) s += d_gw[b * NL + k];
    __shared__ float red[256];
    red[threadIdx.x] = s;
    __syncthreads();
    for (int off = 128; off > 0; off >>= 1) {
        if (threadIdx.x < off) red[threadIdx.x] += red[threadIdx.x + off];
        __syncthreads();
    }
    if (threadIdx.x == 0) out[b] = red[0];
}

// ---------------- launch ----------------
extern "C" void kernel_launch(void* const* d_in, const int* in_sizes, int n_in,
                              void* d_out, int out_size)
{
    const float* pos  = (const float*)d_in[0];   // (8, 2048, 64)
    const float* lw   = (const float*)d_in[1];   // (8, 2048)
    const float* tpos = (const float*)d_in[2];   // (8, 2048, 64)
    const float* tlw  = (const float*)d_in[3];   // (8, 2048)
    float* out = (float*)d_out;                  // (8,)

    prep_kernel<<<(NB * NL + 255) / 256, 256>>>(pos, lw, tpos);

    dim3 g(NL / 128, NB);                        // 128 blocks: one wave
    score_fused<0><<<g, 256>>>(pos, pos, lw);    // self scores -> sparse lists (no dense matrix)

    iterate_kernel<<<NB, 1024>>>(lw);

    score_fused<1><<<g, 256>>>(tpos, pos, tlw);  // cross scores -> d_gw directly

    reduce_kernel<<<NB, 256>>>(out);
}

// round 15
// speedup vs baseline: 8.2152x; 1.2691x over previous
#include <cuda_runtime.h>
#include <cuda_fp16.h>
#include <cstdint>

#define NB 8
#define NL 2048
#define ND 64
#define CAP2 40           // max sparse entries kept per row (diag always in slot 0)
#define STHRESH 35.0f
#define NITER 100
#define RMAX 12           // register-resident entries per row in iterate

// ---------------- static device scratch (no runtime allocation) ----------------
static __device__ float    d_rbA[NB * NL];              // -0.5*||pos||^2
static __device__ float    d_cbA[NB * NL];              // lw - 0.5*||pos||^2
static __device__ float    d_rbC[NB * NL];              // -0.5*||tpos||^2
static __device__ float    d_cbC[NB * NL];              // lw + f - 0.5*||pos||^2 (after iterate)
static __device__ int      d_scnt[NB * NL];             // nnz per row (<= CAP2)
static __device__ float          d_svalT[(size_t)NB * CAP2 * NL];   // transposed lists
static __device__ unsigned short d_scolT[(size_t)NB * CAP2 * NL];
static __device__ unsigned d_MbEnc[NB];                 // encoded per-batch shift max(lw+f)
static __device__ float    d_gw[NB * NL];               // g * exp(tlw) partials
// fp16 hi/lo splits of pos / tpos (3-term HMMA GEMM)
static __device__ __align__(16) __half d_pH[NB * NL * ND];
static __device__ __align__(16) __half d_pL[NB * NL * ND];
static __device__ __align__(16) __half d_tH[NB * NL * ND];
static __device__ __align__(16) __half d_tL[NB * NL * ND];

// ---------------- helpers ----------------
__device__ __forceinline__ unsigned fenc(float f) {
    unsigned u = __float_as_uint(f);
    return (u & 0x80000000u) ? ~u : (u | 0x80000000u);
}
__device__ __forceinline__ float fdec(unsigned e) {
    return __uint_as_float((e & 0x80000000u) ? (e ^ 0x80000000u) : ~e);
}
__device__ __forceinline__ uint32_t smem_u32(const void* p) {
    uint32_t a;
    asm("{ .reg .u64 t; cvta.to.shared.u64 t, %1; cvt.u32.u64 %0, t; }" : "=r"(a) : "l"(p));
    return a;
}
#define SW128(o) ((o) ^ (((o) >> 3) & 0x70))

__device__ __forceinline__ void ldm_x4(unsigned* r, uint32_t addr) {
    asm volatile("ldmatrix.sync.aligned.m8n8.x4.shared.b16 {%0,%1,%2,%3}, [%4];"
                 : "=r"(r[0]), "=r"(r[1]), "=r"(r[2]), "=r"(r[3]) : "r"(addr));
}
__device__ __forceinline__ void mma16816(float* d, const unsigned* a, const unsigned* b) {
    asm("mma.sync.aligned.m16n8k16.row.col.f32.f16.f16.f32 "
        "{%0,%1,%2,%3}, {%4,%5,%6,%7}, {%8,%9}, {%0,%1,%2,%3};"
        : "+f"(d[0]), "+f"(d[1]), "+f"(d[2]), "+f"(d[3])
        : "r"(a[0]), "r"(a[1]), "r"(a[2]), "r"(a[3]), "r"(b[0]), "r"(b[1]));
}

// ---------------- dynamic smem layout (bytes from 1024-aligned base) ----------------
#define SM_AH    0
#define SM_AL    16384
#define SM_BH    32768
#define SM_BL    49152
#define SM_CBS   65536        // 128 f32
#define SM_CA    66048        // 128 int
#define SM_CB    66560
#define SM_BS    67072
#define SM_PS    67584        // 2*128 f32
#define SM_SVAL  68608        // 128*CAP2 f32 = 20480
#define SM_SCOL  89088        // 128*CAP2 u16 = 10240
#define SM_END   99328
#define SMEMSZ   (SM_END + 1024)

// ---------------- prep: norms, biases, fp16 hi/lo splits ----------------
__global__ void prep_kernel(const float* __restrict__ pos,
                            const float* __restrict__ lw,
                            const float* __restrict__ tpos)
{
    int i = blockIdx.x * blockDim.x + threadIdx.x;
    if (i >= NB * NL) return;
    const float* p = pos  + (size_t)i * ND;
    const float* t = tpos + (size_t)i * ND;
    float sp = 0.f, st = 0.f;
#pragma unroll
    for (int d = 0; d < ND; d++) {
        float x = p[d], y = t[d];
        sp += x * x; st += y * y;
        __half xh = __float2half_rn(x);
        __half yh = __float2half_rn(y);
        d_pH[(size_t)i * ND + d] = xh;
        d_pL[(size_t)i * ND + d] = __float2half_rn(x - __half2float(xh));
        d_tH[(size_t)i * ND + d] = yh;
        d_tL[(size_t)i * ND + d] = __float2half_rn(y - __half2float(yh));
    }
    d_rbA[i] = -0.5f * sp;
    d_cbA[i] = lw[i] - 0.5f * sp;
    d_rbC[i] = -0.5f * st;
}

// ---------------- HMMA score pass ----------------
// Block = 128-row stripe of batch b, 8 warps in 4x2 (rowblk x colhalf) grid; loops 16 col tiles.
// P = A.B^T + rowbias + colbias via mma.sync m16n8k16, 3-term fp16 split, fp32 accum.
// PHASE 0 (self, A=pos, B=pos): threshold vs lw_r - STHRESH, shift lw_r, deterministic
//   quad-ballot compaction into per-row lists (diag pinned slot 0).
// PHASE 1 (cross, A=tpos, B=pos): per-row running sums of exp(P - Mb) -> d_gw.
template <int PHASE>
__global__ __launch_bounds__(256, 1) void score_hmma(const float* __restrict__ W)  // lw / tlw
{
    extern __shared__ char smraw[];
    char* sm = (char*)((((uintptr_t)smraw) + 1023) & ~(uintptr_t)1023);
    const uint32_t sb = smem_u32(sm);

    const int b   = blockIdx.y;
    const int rt  = blockIdx.x * 128;
    const int tid = threadIdx.x;
    const int wid = tid >> 5;
    const int lane = tid & 31;
    const int ch  = wid & 1;           // column half (0: cols 0-63, 1: 64-127)
    const int mb  = (wid >> 1) * 32;   // row block base
    const int g   = lane >> 2;         // quad id = row within 8-group
    const int q   = lane & 3;          // lane in quad

    float* cbs = (float*)(sm + SM_CBS);
    int*   s_cA = (int*)(sm + SM_CA);
    int*   s_cB = (int*)(sm + SM_CB);
    int*   s_bs = (int*)(sm + SM_BS);
    float* s_ps = (float*)(sm + SM_PS);
    float* sval = (float*)(sm + SM_SVAL);
    unsigned short* scol = (unsigned short*)(sm + SM_SCOL);

    if (PHASE == 0 && tid < 128) s_bs[tid] = 0;

    // stage A (stripe rows, hi+lo fp16) once, SW128 swizzled
    {
        const char* Ah = (const char*)((PHASE ? d_tH : d_pH) + ((size_t)b * NL + rt) * ND);
        const char* Al = (const char*)((PHASE ? d_tL : d_pL) + ((size_t)b * NL + rt) * ND);
        for (int i = tid; i < 1024; i += 256) {
            int r = i >> 3, s8 = i & 7;
            uint32_t off = (uint32_t)(r * 128 + s8 * 16);
            uint32_t sw = SW128(off);
            *(uint4*)(sm + SM_AH + sw) = *(const uint4*)(Ah + off);
            *(uint4*)(sm + SM_AL + sw) = *(const uint4*)(Al + off);
        }
    }

    // per-thread row slots: s = mt*2 + rh -> local row mb + mt*16 + rh*8 + g
    int rloc[4]; float rbv4[4], lwr4[4];
    float Mb = 0.f;
    if (PHASE == 1) Mb = fdec(d_MbEnc[b]);
    const float* rb = PHASE ? d_rbC : d_rbA;
#pragma unroll
    for (int s = 0; s < 4; s++) {
        int rl = mb + (s >> 1) * 16 + (s & 1) * 8 + g;
        rloc[s] = rl;
        float r0 = rb[b * NL + rt + rl];
        if (PHASE == 0) { lwr4[s] = W[b * NL + rt + rl]; rbv4[s] = r0; }
        else            { rbv4[s] = r0 - Mb; }
    }
    const float* cb = PHASE ? d_cbC : d_cbA;

    // per-lane ldmatrix address components
    const int arow = lane & 15;               // + mb + mt*16
    const int acs  = lane >> 4;               // A chunk select
    const int nrow = ((lane >> 4) << 3) + (lane & 7);   // + ch*64 + np*16
    const int bcs  = (lane >> 3) & 1;         // B chunk select

    float rs[4] = {0.f, 0.f, 0.f, 0.f};       // PHASE 1 per-row running sums

    for (int t = 0; t < 16; t++) {
        const int ct = t * 128;
        // stage B tile (128 cols of pos, hi+lo) + column biases
        {
            const char* Bh = (const char*)(d_pH + ((size_t)b * NL + ct) * ND);
            const char* Bl = (const char*)(d_pL + ((size_t)b * NL + ct) * ND);
            for (int i = tid; i < 1024; i += 256) {
                int r = i >> 3, s8 = i & 7;
                uint32_t off = (uint32_t)(r * 128 + s8 * 16);
                uint32_t sw = SW128(off);
                *(uint4*)(sm + SM_BH + sw) = *(const uint4*)(Bh + off);
                *(uint4*)(sm + SM_BL + sw) = *(const uint4*)(Bl + off);
            }
            if (tid < 128) cbs[tid] = cb[b * NL + ct + tid];
        }
        __syncthreads();

        // -------- mainloop: 3-term HMMA --------
        float acc[2][8][4];
#pragma unroll
        for (int mt = 0; mt < 2; mt++)
#pragma unroll
            for (int nt = 0; nt < 8; nt++)
#pragma unroll
                for (int e = 0; e < 4; e++) acc[mt][nt][e] = 0.f;

#pragma unroll
        for (int kc = 0; kc < 8; kc += 2) {      // k-steps of 16 halves (2 chunks)
            unsigned ah[2][4], al[2][4];
#pragma unroll
            for (int mt = 0; mt < 2; mt++) {
                uint32_t off = (uint32_t)((mb + mt * 16 + arow) * 128 + (kc + acs) * 16);
                uint32_t sw = SW128(off);
                ldm_x4(ah[mt], sb + SM_AH + sw);
                ldm_x4(al[mt], sb + SM_AL + sw);
            }
#pragma unroll
            for (int np = 0; np < 4; np++) {
                unsigned bh[4], bl[4];
                uint32_t off = (uint32_t)((ch * 64 + np * 16 + nrow) * 128 + (kc + bcs) * 16);
                uint32_t sw = SW128(off);
                ldm_x4(bh, sb + SM_BH + sw);
                ldm_x4(bl, sb + SM_BL + sw);
#pragma unroll
                for (int mt = 0; mt < 2; mt++)
#pragma unroll
                    for (int t2 = 0; t2 < 2; t2++) {
                        float* d = acc[mt][np * 2 + t2];
                        mma16816(d, ah[mt], &bh[2 * t2]);   // hh
                        mma16816(d, ah[mt], &bl[2 * t2]);   // hl
                        mma16816(d, al[mt], &bh[2 * t2]);   // lh
                    }
            }
        }

        // -------- per-tile epilogue --------
        if (PHASE == 0) {
            // count phase (+ diag pin to slot 0)
            int cnt[4] = {0, 0, 0, 0};
#pragma unroll
            for (int mt = 0; mt < 2; mt++)
#pragma unroll
                for (int rh = 0; rh < 2; rh++) {
                    const int s = mt * 2 + rh;
                    const int grow = rt + rloc[s];
                    const float thr = lwr4[s] - STHRESH;
#pragma unroll
                    for (int nt = 0; nt < 8; nt++)
#pragma unroll
                        for (int c = 0; c < 2; c++) {
                            int cl = ch * 64 + nt * 8 + 2 * q + c;
                            float v = acc[mt][nt][rh * 2 + c] + rbv4[s] + cbs[cl];
                            int gcol = ct + cl;
                            bool isd  = (gcol == grow);
                            bool keep = (v > thr) && !isd;
                            unsigned bm = __ballot_sync(0xFFFFFFFFu, keep);
                            if (isd) {
                                sval[rloc[s] * CAP2] = __expf(v - lwr4[s]);
                                scol[rloc[s] * CAP2] = (unsigned short)gcol;
                            }
                            cnt[s] += __popc((bm >> (g * 4)) & 0xFu);
                        }
                }
            if (q == 0) {
#pragma unroll
                for (int s = 0; s < 4; s++) {
                    if (ch == 0) s_cA[rloc[s]] = cnt[s];
                    else         s_cB[rloc[s]] = cnt[s];
                }
            }
            __syncthreads();
            // write phase (half A first, then half B; fixed scan order)
            int ws[4];
#pragma unroll
            for (int s = 0; s < 4; s++)
                ws[s] = 1 + s_bs[rloc[s]] + (ch ? s_cA[rloc[s]] : 0);
#pragma unroll
            for (int mt = 0; mt < 2; mt++)
#pragma unroll
                for (int rh = 0; rh < 2; rh++) {
                    const int s = mt * 2 + rh;
                    const int grow = rt + rloc[s];
                    const float thr = lwr4[s] - STHRESH;
#pragma unroll
                    for (int nt = 0; nt < 8; nt++)
#pragma unroll
                        for (int c = 0; c < 2; c++) {
                            int cl = ch * 64 + nt * 8 + 2 * q + c;
                            float v = acc[mt][nt][rh * 2 + c] + rbv4[s] + cbs[cl];
                            int gcol = ct + cl;
                            bool keep = (v > thr) && (gcol != grow);
                            unsigned bm = __ballot_sync(0xFFFFFFFFu, keep);
                            unsigned nib = (bm >> (g * 4)) & 0xFu;
                            if (keep) {
                                int pos = ws[s] + __popc(nib & ((1u << q) - 1u));
                                if (pos < CAP2) {
                                    sval[rloc[s] * CAP2 + pos] = __expf(v - lwr4[s]);
                                    scol[rloc[s] * CAP2 + pos] = (unsigned short)gcol;
                                }
                            }
                            ws[s] += __popc(nib);
                        }
                }
            __syncthreads();
            if (ch == 0 && q == 0) {
#pragma unroll
                for (int s = 0; s < 4; s++)
                    s_bs[rloc[s]] += s_cA[rloc[s]] + s_cB[rloc[s]];
            }
            __syncthreads();
        } else {
#pragma unroll
            for (int mt = 0; mt < 2; mt++)
#pragma unroll
                for (int rh = 0; rh < 2; rh++) {
                    const int s = mt * 2 + rh;
#pragma unroll
                    for (int nt = 0; nt < 8; nt++)
#pragma unroll
                        for (int c = 0; c < 2; c++) {
                            int cl = ch * 64 + nt * 8 + 2 * q + c;
                            rs[s] += __expf(acc[mt][nt][rh * 2 + c] + rbv4[s] + cbs[cl]);
                        }
                }
            __syncthreads();   // all cbs/B reads done before next stage overwrites
        }
    }

    // -------- final epilogue --------
    if (PHASE == 0) {
        // coalesced transposed write of the lists
        for (int idx = tid; idx < 128 * CAP2; idx += 256) {
            int j  = idx >> 7;
            int rr = idx & 127;
            int c = 1 + s_bs[rr]; if (c > CAP2) c = CAP2;
            size_t o = ((size_t)b * CAP2 + j) * NL + rt + rr;
            d_svalT[o] = (j < c) ? sval[rr * CAP2 + j] : 0.f;
            d_scolT[o] = (j < c) ? scol[rr * CAP2 + j] : (unsigned short)0;
        }
        if (tid < 128) {
            int c = 1 + s_bs[tid]; if (c > CAP2) c = CAP2;
            d_scnt[b * NL + rt + tid] = c;
        }
    } else {
#pragma unroll
        for (int s = 0; s < 4; s++) {
            float v = rs[s];
            v += __shfl_xor_sync(0xFFFFFFFFu, v, 1);
            v += __shfl_xor_sync(0xFFFFFFFFu, v, 2);
            if (q == 0) s_ps[ch * 128 + rloc[s]] = v;
        }
        __syncthreads();
        if (tid < 128) {
            float ssum = s_ps[tid] + s_ps[128 + tid];
            float gg = -(Mb + __logf(ssum));
            d_gw[b * NL + rt + tid] = gg * __expf(W[b * NL + rt + tid]);
        }
    }
}

// ---------------- iterations: one block per batch, lists register-resident ----------------
__global__ __launch_bounds__(1024, 1) void iterate_kernel(const float* __restrict__ lw)
{
    const int b   = blockIdx.x;
    const int tid = threadIdx.x;
    __shared__ float us[NL];            // exp(f)
    __shared__ unsigned conv;
    __shared__ unsigned mbred;

    if (tid == 0) { conv = 0u; mbred = 0u; }

    const int r0 = tid, r1 = tid + 1024;
    const float lw0 = lw[b * NL + r0];
    const float lw1 = lw[b * NL + r1];
    const float m0 = lw0, m1 = lw1;     // shift = lw_r (matches sparse-build shift)
    const int   n0 = d_scnt[b * NL + r0];
    const int   n1 = d_scnt[b * NL + r1];

    float v0[RMAX], v1[RMAX];
    int   cp0[RMAX / 2], cp1[RMAX / 2];

    {
        int ctmp0[RMAX], ctmp1[RMAX];
#pragma unroll
        for (int j = 0; j < RMAX; j++) {
            size_t i0 = ((size_t)b * CAP2 + j) * NL + r0;
            size_t i1 = ((size_t)b * CAP2 + j) * NL + r1;
            bool k0 = (j < n0), k1 = (j < n1);
            v0[j]    = k0 ? d_svalT[i0] : 0.f;
            ctmp0[j] = k0 ? (int)d_scolT[i0] : 0;
            v1[j]    = k1 ? d_svalT[i1] : 0.f;
            ctmp1[j] = k1 ? (int)d_scolT[i1] : 0;
        }
#pragma unroll
        for (int h = 0; h < RMAX / 2; h++) {
            cp0[h] = ctmp0[2 * h] | (ctmp0[2 * h + 1] << 16);
            cp1[h] = ctmp1[2 * h] | (ctmp1[2 * h + 1] << 16);
        }
    }

    float f0 = 0.f, f1 = 0.f;
    __syncthreads();

    for (int it = 0; it < NITER; it++) {
        us[r0] = __expf(f0);
        us[r1] = __expf(f1);
        __syncthreads();

        float s0 = 0.f, s1 = 0.f;
#pragma unroll
        for (int h = 0; h < RMAX / 2; h++) {
            int p0 = cp0[h], p1 = cp1[h];
            s0 = fmaf(v0[2 * h],     us[p0 & 0xFFFF], s0);
            s0 = fmaf(v0[2 * h + 1], us[p0 >> 16],    s0);
            s1 = fmaf(v1[2 * h],     us[p1 & 0xFFFF], s1);
            s1 = fmaf(v1[2 * h + 1], us[p1 >> 16],    s1);
        }
        for (int j = RMAX; j < n0; j++) {
            size_t idx = ((size_t)b * CAP2 + j) * NL + r0;
            s0 = fmaf(d_svalT[idx], us[d_scolT[idx]], s0);
        }
        for (int j = RMAX; j < n1; j++) {
            size_t idx = ((size_t)b * CAP2 + j) * NL + r1;
            s1 = fmaf(d_svalT[idx], us[d_scolT[idx]], s1);
        }

        float fn0 = 0.5f * (f0 - m0 - __logf(s0));
        float fn1 = 0.5f * (f1 - m1 - __logf(s1));
        float dmax = fmaxf(fabsf(fn0 - f0), fabsf(fn1 - f1));
        __syncthreads();
        f0 = fn0;
        f1 = fn1;

        if ((it & 3) == 3 && it < NITER - 1) {
#pragma unroll
            for (int off = 16; off > 0; off >>= 1)
                dmax = fmaxf(dmax, __shfl_xor_sync(0xFFFFFFFFu, dmax, off));
            if ((tid & 31) == 0) atomicMax(&conv, fenc(dmax));
            __syncthreads();
            bool stop = fdec(conv) < 1e-6f;
            __syncthreads();
            if (tid == 0) conv = 0u;
            if (stop) break;
        }
    }

    // per-batch shift for the cross pass: Mb = max_k(lw_k + f_k)
    float lf = fmaxf(lw0 + f0, lw1 + f1);
#pragma unroll
    for (int off = 16; off > 0; off >>= 1)
        lf = fmaxf(lf, __shfl_xor_sync(0xFFFFFFFFu, lf, off));
    if ((tid & 31) == 0) atomicMax(&mbred, fenc(lf));

    d_cbC[b * NL + r0] = lw0 + f0 + d_rbA[b * NL + r0];
    d_cbC[b * NL + r1] = lw1 + f1 + d_rbA[b * NL + r1];

    __syncthreads();
    if (tid == 0) d_MbEnc[b] = mbred;
}

// ---------------- deterministic final reduction ----------------
__global__ __launch_bounds__(256) void reduce_kernel(float* __restrict__ out)
{
    const int b = blockIdx.x;
    float s = 0.f;
    for (int k = threadIdx.x; k < NL; k += 256) s += d_gw[b * NL + k];
    __shared__ float red[256];
    red[threadIdx.x] = s;
    __syncthreads();
    for (int off = 128; off > 0; off >>= 1) {
        if (threadIdx.x < off) red[threadIdx.x] += red[threadIdx.x + off];
        __syncthreads();
    }
    if (threadIdx.x == 0) out[b] = red[0];
}

// ---------------- launch ----------------
extern "C" void kernel_launch(void* const* d_in, const int* in_sizes, int n_in,
                              void* d_out, int out_size)
{
    const float* pos  = (const float*)d_in[0];   // (8, 2048, 64)
    const float* lw   = (const float*)d_in[1];   // (8, 2048)
    const float* tpos = (const float*)d_in[2];   // (8, 2048, 64)
    const float* tlw  = (const float*)d_in[3];   // (8, 2048)
    float* out = (float*)d_out;                  // (8,)

    cudaFuncSetAttribute(score_hmma<0>, cudaFuncAttributeMaxDynamicSharedMemorySize, SMEMSZ);
    cudaFuncSetAttribute(score_hmma<1>, cudaFuncAttributeMaxDynamicSharedMemorySize, SMEMSZ);

    prep_kernel<<<(NB * NL + 255) / 256, 256>>>(pos, lw, tpos);

    dim3 g(NL / 128, NB);                        // 128 blocks: one wave
    score_hmma<0><<<g, 256, SMEMSZ>>>(lw);       // self scores -> sparse lists

    iterate_kernel<<<NB, 1024>>>(lw);

    score_hmma<1><<<g, 256, SMEMSZ>>>(tlw);      // cross scores -> d_gw

    reduce_kernel<<<NB, 256>>>(out);
}

// round 16
// speedup vs baseline: 10.5187x; 1.2804x over previous
#include <cuda_runtime.h>
#include <cuda_fp16.h>
#include <cstdint>

#define NB 8
#define NL 2048
#define ND 64
#define CAP2 40           // max sparse entries kept per row (diag always in slot 0)
#define STHRESH 35.0f
#define NITER 100
#define RMAX 12           // register-resident entries per row in iterate

// ---------------- static device scratch (no runtime allocation) ----------------
static __device__ float    d_rbA[NB * NL];              // -0.5*||pos||^2
static __device__ float    d_cbA[NB * NL];              // lw - 0.5*||pos||^2
static __device__ float    d_rbC[NB * NL];              // -0.5*||tpos||^2
static __device__ float    d_cbC[NB * NL];              // lw + f - 0.5*||pos||^2 (after iterate)
static __device__ int      d_scnt[NB * NL];             // nnz per row (<= CAP2)
static __device__ float          d_svalT[(size_t)NB * CAP2 * NL];   // transposed lists
static __device__ unsigned short d_scolT[(size_t)NB * CAP2 * NL];
static __device__ unsigned d_MbEnc[NB];                 // encoded per-batch shift max(lw+f)
static __device__ float    d_gw[NB * NL];               // g * exp(tlw) partials
// fp16 hi/lo splits of pos / tpos (3-term HMMA GEMM)
static __device__ __align__(16) __half d_pH[NB * NL * ND];
static __device__ __align__(16) __half d_pL[NB * NL * ND];
static __device__ __align__(16) __half d_tH[NB * NL * ND];
static __device__ __align__(16) __half d_tL[NB * NL * ND];

// ---------------- helpers ----------------
__device__ __forceinline__ unsigned fenc(float f) {
    unsigned u = __float_as_uint(f);
    return (u & 0x80000000u) ? ~u : (u | 0x80000000u);
}
__device__ __forceinline__ float fdec(unsigned e) {
    return __uint_as_float((e & 0x80000000u) ? (e ^ 0x80000000u) : ~e);
}
__device__ __forceinline__ uint32_t smem_u32(const void* p) {
    uint32_t a;
    asm("{ .reg .u64 t; cvta.to.shared.u64 t, %1; cvt.u32.u64 %0, t; }" : "=r"(a) : "l"(p));
    return a;
}
#define SW128(o) ((o) ^ (((o) >> 3) & 0x70))

__device__ __forceinline__ void ldm_x4(unsigned* r, uint32_t addr) {
    asm volatile("ldmatrix.sync.aligned.m8n8.x4.shared.b16 {%0,%1,%2,%3}, [%4];"
                 : "=r"(r[0]), "=r"(r[1]), "=r"(r[2]), "=r"(r[3]) : "r"(addr));
}
__device__ __forceinline__ void mma16816(float* d, const unsigned* a, const unsigned* b) {
    asm("mma.sync.aligned.m16n8k16.row.col.f32.f16.f16.f32 "
        "{%0,%1,%2,%3}, {%4,%5,%6,%7}, {%8,%9}, {%0,%1,%2,%3};"
        : "+f"(d[0]), "+f"(d[1]), "+f"(d[2]), "+f"(d[3])
        : "r"(a[0]), "r"(a[1]), "r"(a[2]), "r"(a[3]), "r"(b[0]), "r"(b[1]));
}

// ---------------- dynamic smem layout (bytes from 1024-aligned base) ----------------
#define SM_AH    0            // 128x64 half = 16384
#define SM_AL    16384
#define SM_BH    32768
#define SM_BL    49152
#define SM_CBS   65536        // 128 f32
#define SM_C     66048        // 128*4 int (per-quarter counts) = 2048
#define SM_BS    68096        // 128 int
#define SM_PS    68608        // 4*128 f32 = 2048
#define SM_SVAL  70656        // 128*CAP2 f32 = 20480
#define SM_SCOL  91136        // 128*CAP2 u16 = 10240
#define SM_END   101376
#define SMEMSZ   (SM_END + 1024)

// ---------------- prep: norms, biases, fp16 hi/lo splits ----------------
__global__ void prep_kernel(const float* __restrict__ pos,
                            const float* __restrict__ lw,
                            const float* __restrict__ tpos)
{
    int i = blockIdx.x * blockDim.x + threadIdx.x;
    if (i >= NB * NL) return;
    const float* p = pos  + (size_t)i * ND;
    const float* t = tpos + (size_t)i * ND;
    float sp = 0.f, st = 0.f;
#pragma unroll
    for (int d = 0; d < ND; d++) {
        float x = p[d], y = t[d];
        sp += x * x; st += y * y;
        __half xh = __float2half_rn(x);
        __half yh = __float2half_rn(y);
        d_pH[(size_t)i * ND + d] = xh;
        d_pL[(size_t)i * ND + d] = __float2half_rn(x - __half2float(xh));
        d_tH[(size_t)i * ND + d] = yh;
        d_tL[(size_t)i * ND + d] = __float2half_rn(y - __half2float(yh));
    }
    d_rbA[i] = -0.5f * sp;
    d_cbA[i] = lw[i] - 0.5f * sp;
    d_rbC[i] = -0.5f * st;
}

// ---------------- HMMA score pass ----------------
// Block = 128-row stripe of batch b, 16 warps in 4x4 (rowgroup x colquarter) grid; 16 col tiles.
// P = A.B^T + rowbias + colbias via mma.sync m16n8k16, 3-term fp16 split, fp32 accum.
// PHASE 0 (self): threshold vs lw_r - STHRESH, shift lw_r, deterministic quad-ballot
//   compaction into per-row lists (diag pinned slot 0).
// PHASE 1 (cross): per-row running sums of exp(P - Mb) -> d_gw.
template <int PHASE>
__global__ __launch_bounds__(512, 1) void score_hmma(const float* __restrict__ W)  // lw / tlw
{
    extern __shared__ char smraw[];
    char* sm = (char*)((((uintptr_t)smraw) + 1023) & ~(uintptr_t)1023);
    const uint32_t sb = smem_u32(sm);

    const int b   = blockIdx.y;
    const int rt  = blockIdx.x * 128;
    const int tid = threadIdx.x;
    const int wid = tid >> 5;
    const int lane = tid & 31;
    const int cq  = wid & 3;           // column quarter (cols [cq*32, cq*32+32))
    const int mb  = (wid >> 2) * 32;   // row group base
    const int g   = lane >> 2;         // quad id
    const int q   = lane & 3;          // lane in quad

    float* cbs = (float*)(sm + SM_CBS);
    int*   s_c  = (int*)(sm + SM_C);    // [row][quarter]
    int*   s_bs = (int*)(sm + SM_BS);
    float* s_ps = (float*)(sm + SM_PS); // [quarter][row]
    float* sval = (float*)(sm + SM_SVAL);
    unsigned short* scol = (unsigned short*)(sm + SM_SCOL);

    if (PHASE == 0 && tid < 128) s_bs[tid] = 0;

    // stage A (stripe rows, hi+lo fp16) once, SW128 swizzled
    {
        const char* Ah = (const char*)((PHASE ? d_tH : d_pH) + ((size_t)b * NL + rt) * ND);
        const char* Al = (const char*)((PHASE ? d_tL : d_pL) + ((size_t)b * NL + rt) * ND);
        for (int i = tid; i < 1024; i += 512) {
            int r = i >> 3, s8 = i & 7;
            uint32_t off = (uint32_t)(r * 128 + s8 * 16);
            uint32_t sw = SW128(off);
            *(uint4*)(sm + SM_AH + sw) = *(const uint4*)(Ah + off);
            *(uint4*)(sm + SM_AL + sw) = *(const uint4*)(Al + off);
        }
    }

    // per-thread row slots: s = mt*2 + rh -> local row mb + mt*16 + rh*8 + g
    int rloc[4]; float rbv4[4], lwr4[4];
    float Mb = 0.f;
    if (PHASE == 1) Mb = fdec(d_MbEnc[b]);
    const float* rb = PHASE ? d_rbC : d_rbA;
#pragma unroll
    for (int s = 0; s < 4; s++) {
        int rl = mb + (s >> 1) * 16 + (s & 1) * 8 + g;
        rloc[s] = rl;
        float r0 = rb[b * NL + rt + rl];
        if (PHASE == 0) { lwr4[s] = W[b * NL + rt + rl]; rbv4[s] = r0; }
        else            { rbv4[s] = r0 - Mb; }
    }
    const float* cb = PHASE ? d_cbC : d_cbA;

    // per-lane ldmatrix address components
    const int arow = lane & 15;               // + mb + mt*16
    const int acs  = lane >> 4;               // A chunk select
    const int nrow = ((lane >> 4) << 3) + (lane & 7);   // + cq*32 + np*16
    const int bcs  = (lane >> 3) & 1;         // B chunk select

    float rs[4] = {0.f, 0.f, 0.f, 0.f};       // PHASE 1 per-row running sums

    for (int t = 0; t < 16; t++) {
        const int ct = t * 128;
        // stage B tile (128 cols of pos, hi+lo) + column biases
        {
            const char* Bh = (const char*)(d_pH + ((size_t)b * NL + ct) * ND);
            const char* Bl = (const char*)(d_pL + ((size_t)b * NL + ct) * ND);
            for (int i = tid; i < 1024; i += 512) {
                int r = i >> 3, s8 = i & 7;
                uint32_t off = (uint32_t)(r * 128 + s8 * 16);
                uint32_t sw = SW128(off);
                *(uint4*)(sm + SM_BH + sw) = *(const uint4*)(Bh + off);
                *(uint4*)(sm + SM_BL + sw) = *(const uint4*)(Bl + off);
            }
            if (tid < 128) cbs[tid] = cb[b * NL + ct + tid];
        }
        __syncthreads();

        // -------- mainloop: 3-term HMMA, M=32 N=32 per warp --------
        float acc[2][4][4];
#pragma unroll
        for (int mt = 0; mt < 2; mt++)
#pragma unroll
            for (int nt = 0; nt < 4; nt++)
#pragma unroll
                for (int e = 0; e < 4; e++) acc[mt][nt][e] = 0.f;

#pragma unroll
        for (int kc = 0; kc < 8; kc += 2) {
            unsigned ah[2][4], al[2][4];
#pragma unroll
            for (int mt = 0; mt < 2; mt++) {
                uint32_t off = (uint32_t)((mb + mt * 16 + arow) * 128 + (kc + acs) * 16);
                uint32_t sw = SW128(off);
                ldm_x4(ah[mt], sb + SM_AH + sw);
                ldm_x4(al[mt], sb + SM_AL + sw);
            }
#pragma unroll
            for (int np = 0; np < 2; np++) {
                unsigned bh[4], bl[4];
                uint32_t off = (uint32_t)((cq * 32 + np * 16 + nrow) * 128 + (kc + bcs) * 16);
                uint32_t sw = SW128(off);
                ldm_x4(bh, sb + SM_BH + sw);
                ldm_x4(bl, sb + SM_BL + sw);
#pragma unroll
                for (int mt = 0; mt < 2; mt++)
#pragma unroll
                    for (int t2 = 0; t2 < 2; t2++) {
                        float* d = acc[mt][np * 2 + t2];
                        mma16816(d, ah[mt], &bh[2 * t2]);   // hh
                        mma16816(d, ah[mt], &bl[2 * t2]);   // hl
                        mma16816(d, al[mt], &bh[2 * t2]);   // lh
                    }
            }
        }

        // -------- per-tile epilogue --------
        if (PHASE == 0) {
            // count phase (+ diag pin to slot 0)
            int cnt[4] = {0, 0, 0, 0};
#pragma unroll
            for (int mt = 0; mt < 2; mt++)
#pragma unroll
                for (int rh = 0; rh < 2; rh++) {
                    const int s = mt * 2 + rh;
                    const int grow = rt + rloc[s];
                    const float thr = lwr4[s] - STHRESH;
#pragma unroll
                    for (int nt = 0; nt < 4; nt++)
#pragma unroll
                        for (int c = 0; c < 2; c++) {
                            int cl = cq * 32 + nt * 8 + 2 * q + c;
                            float v = acc[mt][nt][rh * 2 + c] + rbv4[s] + cbs[cl];
                            int gcol = ct + cl;
                            bool isd  = (gcol == grow);
                            bool keep = (v > thr) && !isd;
                            unsigned bm = __ballot_sync(0xFFFFFFFFu, keep);
                            if (isd) {
                                sval[rloc[s] * CAP2] = __expf(v - lwr4[s]);
                                scol[rloc[s] * CAP2] = (unsigned short)gcol;
                            }
                            cnt[s] += __popc((bm >> (g * 4)) & 0xFu);
                        }
                }
            if (q == 0) {
#pragma unroll
                for (int s = 0; s < 4; s++) s_c[rloc[s] * 4 + cq] = cnt[s];
            }
            __syncthreads();
            // write phase: quarter-ordered deterministic offsets
            int ws[4];
#pragma unroll
            for (int s = 0; s < 4; s++) {
                int off0 = 1 + s_bs[rloc[s]];
#pragma unroll
                for (int qq = 0; qq < 4; qq++)
                    if (qq < cq) off0 += s_c[rloc[s] * 4 + qq];
                ws[s] = off0;
            }
#pragma unroll
            for (int mt = 0; mt < 2; mt++)
#pragma unroll
                for (int rh = 0; rh < 2; rh++) {
                    const int s = mt * 2 + rh;
                    const int grow = rt + rloc[s];
                    const float thr = lwr4[s] - STHRESH;
#pragma unroll
                    for (int nt = 0; nt < 4; nt++)
#pragma unroll
                        for (int c = 0; c < 2; c++) {
                            int cl = cq * 32 + nt * 8 + 2 * q + c;
                            float v = acc[mt][nt][rh * 2 + c] + rbv4[s] + cbs[cl];
                            int gcol = ct + cl;
                            bool keep = (v > thr) && (gcol != grow);
                            unsigned bm = __ballot_sync(0xFFFFFFFFu, keep);
                            unsigned nib = (bm >> (g * 4)) & 0xFu;
                            if (keep) {
                                int pos = ws[s] + __popc(nib & ((1u << q) - 1u));
                                if (pos < CAP2) {
                                    sval[rloc[s] * CAP2 + pos] = __expf(v - lwr4[s]);
                                    scol[rloc[s] * CAP2 + pos] = (unsigned short)gcol;
                                }
                            }
                            ws[s] += __popc(nib);
                        }
                }
            __syncthreads();
            if (cq == 0 && q == 0) {
#pragma unroll
                for (int s = 0; s < 4; s++)
                    s_bs[rloc[s]] += s_c[rloc[s] * 4 + 0] + s_c[rloc[s] * 4 + 1]
                                   + s_c[rloc[s] * 4 + 2] + s_c[rloc[s] * 4 + 3];
            }
            __syncthreads();
        } else {
#pragma unroll
            for (int mt = 0; mt < 2; mt++)
#pragma unroll
                for (int rh = 0; rh < 2; rh++) {
                    const int s = mt * 2 + rh;
#pragma unroll
                    for (int nt = 0; nt < 4; nt++)
#pragma unroll
                        for (int c = 0; c < 2; c++) {
                            int cl = cq * 32 + nt * 8 + 2 * q + c;
                            rs[s] += __expf(acc[mt][nt][rh * 2 + c] + rbv4[s] + cbs[cl]);
                        }
                }
            __syncthreads();   // all cbs/B reads done before next stage overwrites
        }
    }

    // -------- final epilogue --------
    if (PHASE == 0) {
        // coalesced transposed write of the lists
        for (int idx = tid; idx < 128 * CAP2; idx += 512) {
            int j  = idx >> 7;
            int rr = idx & 127;
            int c = 1 + s_bs[rr]; if (c > CAP2) c = CAP2;
            size_t o = ((size_t)b * CAP2 + j) * NL + rt + rr;
            d_svalT[o] = (j < c) ? sval[rr * CAP2 + j] : 0.f;
            d_scolT[o] = (j < c) ? scol[rr * CAP2 + j] : (unsigned short)0;
        }
        if (tid < 128) {
            int c = 1 + s_bs[tid]; if (c > CAP2) c = CAP2;
            d_scnt[b * NL + rt + tid] = c;
        }
    } else {
#pragma unroll
        for (int s = 0; s < 4; s++) {
            float v = rs[s];
            v += __shfl_xor_sync(0xFFFFFFFFu, v, 1);
            v += __shfl_xor_sync(0xFFFFFFFFu, v, 2);
            if (q == 0) s_ps[cq * 128 + rloc[s]] = v;
        }
        __syncthreads();
        if (tid < 128) {
            float ssum = s_ps[tid] + s_ps[128 + tid] + s_ps[256 + tid] + s_ps[384 + tid];
            float gg = -(Mb + __logf(ssum));
            d_gw[b * NL + rt + tid] = gg * __expf(W[b * NL + rt + tid]);
        }
    }
}

// ---------------- iterations: one block per batch, lists register-resident ----------------
__global__ __launch_bounds__(1024, 1) void iterate_kernel(const float* __restrict__ lw)
{
    const int b   = blockIdx.x;
    const int tid = threadIdx.x;
    __shared__ float us[NL];            // exp(f)
    __shared__ unsigned conv;
    __shared__ unsigned mbred;

    if (tid == 0) { conv = 0u; mbred = 0u; }

    const int r0 = tid, r1 = tid + 1024;
    const float lw0 = lw[b * NL + r0];
    const float lw1 = lw[b * NL + r1];
    const float m0 = lw0, m1 = lw1;     // shift = lw_r (matches sparse-build shift)
    const int   n0 = d_scnt[b * NL + r0];
    const int   n1 = d_scnt[b * NL + r1];

    float v0[RMAX], v1[RMAX];
    int   cp0[RMAX / 2], cp1[RMAX / 2];

    {
        int ctmp0[RMAX], ctmp1[RMAX];
#pragma unroll
        for (int j = 0; j < RMAX; j++) {
            size_t i0 = ((size_t)b * CAP2 + j) * NL + r0;
            size_t i1 = ((size_t)b * CAP2 + j) * NL + r1;
            bool k0 = (j < n0), k1 = (j < n1);
            v0[j]    = k0 ? d_svalT[i0] : 0.f;
            ctmp0[j] = k0 ? (int)d_scolT[i0] : 0;
            v1[j]    = k1 ? d_svalT[i1] : 0.f;
            ctmp1[j] = k1 ? (int)d_scolT[i1] : 0;
        }
#pragma unroll
        for (int h = 0; h < RMAX / 2; h++) {
            cp0[h] = ctmp0[2 * h] | (ctmp0[2 * h + 1] << 16);
            cp1[h] = ctmp1[2 * h] | (ctmp1[2 * h + 1] << 16);
        }
    }

    float f0 = 0.f, f1 = 0.f;
    __syncthreads();

    for (int it = 0; it < NITER; it++) {
        us[r0] = __expf(f0);
        us[r1] = __expf(f1);
        __syncthreads();

        float s0 = 0.f, s1 = 0.f;
#pragma unroll
        for (int h = 0; h < RMAX / 2; h++) {
            int p0 = cp0[h], p1 = cp1[h];
            s0 = fmaf(v0[2 * h],     us[p0 & 0xFFFF], s0);
            s0 = fmaf(v0[2 * h + 1], us[p0 >> 16],    s0);
            s1 = fmaf(v1[2 * h],     us[p1 & 0xFFFF], s1);
            s1 = fmaf(v1[2 * h + 1], us[p1 >> 16],    s1);
        }
        for (int j = RMAX; j < n0; j++) {
            size_t idx = ((size_t)b * CAP2 + j) * NL + r0;
            s0 = fmaf(d_svalT[idx], us[d_scolT[idx]], s0);
        }
        for (int j = RMAX; j < n1; j++) {
            size_t idx = ((size_t)b * CAP2 + j) * NL + r1;
            s1 = fmaf(d_svalT[idx], us[d_scolT[idx]], s1);
        }

        float fn0 = 0.5f * (f0 - m0 - __logf(s0));
        float fn1 = 0.5f * (f1 - m1 - __logf(s1));
        float dmax = fmaxf(fabsf(fn0 - f0), fabsf(fn1 - f1));
        __syncthreads();
        f0 = fn0;
        f1 = fn1;

        if ((it & 3) == 3 && it < NITER - 1) {
#pragma unroll
            for (int off = 16; off > 0; off >>= 1)
                dmax = fmaxf(dmax, __shfl_xor_sync(0xFFFFFFFFu, dmax, off));
            if ((tid & 31) == 0) atomicMax(&conv, fenc(dmax));
            __syncthreads();
            bool stop = fdec(conv) < 1e-6f;
            __syncthreads();
            if (tid == 0) conv = 0u;
            if (stop) break;
        }
    }

    // per-batch shift for the cross pass: Mb = max_k(lw_k + f_k)
    float lf = fmaxf(lw0 + f0, lw1 + f1);
#pragma unroll
    for (int off = 16; off > 0; off >>= 1)
        lf = fmaxf(lf, __shfl_xor_sync(0xFFFFFFFFu, lf, off));
    if ((tid & 31) == 0) atomicMax(&mbred, fenc(lf));

    d_cbC[b * NL + r0] = lw0 + f0 + d_rbA[b * NL + r0];
    d_cbC[b * NL + r1] = lw1 + f1 + d_rbA[b * NL + r1];

    __syncthreads();
    if (tid == 0) d_MbEnc[b] = mbred;
}

// ---------------- deterministic final reduction ----------------
__global__ __launch_bounds__(256) void reduce_kernel(float* __restrict__ out)
{
    const int b = blockIdx.x;
    float s = 0.f;
    for (int k = threadIdx.x; k < NL; k += 256) s += d_gw[b * NL + k];
    __shared__ float red[256];
    red[threadIdx.x] = s;
    __syncthreads();
    for (int off = 128; off > 0; off >>= 1) {
        if (threadIdx.x < off) red[threadIdx.x] += red[threadIdx.x + off];
        __syncthreads();
    }
    if (threadIdx.x == 0) out[b] = red[0];
}

// ---------------- launch ----------------
extern "C" void kernel_launch(void* const* d_in, const int* in_sizes, int n_in,
                              void* d_out, int out_size)
{
    const float* pos  = (const float*)d_in[0];   // (8, 2048, 64)
    const float* lw   = (const float*)d_in[1];   // (8, 2048)
    const float* tpos = (const float*)d_in[2];   // (8, 2048, 64)
    const float* tlw  = (const float*)d_in[3];   // (8, 2048)
    float* out = (float*)d_out;                  // (8,)

    cudaFuncSetAttribute(score_hmma<0>, cudaFuncAttributeMaxDynamicSharedMemorySize, SMEMSZ);
    cudaFuncSetAttribute(score_hmma<1>, cudaFuncAttributeMaxDynamicSharedMemorySize, SMEMSZ);

    prep_kernel<<<(NB * NL + 255) / 256, 256>>>(pos, lw, tpos);

    dim3 g(NL / 128, NB);                        // 128 blocks: one wave
    score_hmma<0><<<g, 512, SMEMSZ>>>(lw);       // self scores -> sparse lists

    iterate_kernel<<<NB, 1024>>>(lw);

    score_hmma<1><<<g, 512, SMEMSZ>>>(tlw);      // cross scores -> d_gw

    reduce_kernel<<<NB, 256>>>(out);
}

// round 17
// speedup vs baseline: 11.9321x; 1.1344x over previous
#include <cuda_runtime.h>
#include <cuda_fp16.h>
#include <cstdint>

#define NB 8
#define NL 2048
#define ND 64
#define CAP2 40           // max sparse entries kept per row (diag always in slot 0)
#define STHRESH 35.0f
#define NITER 100
#define RMAX 12           // register-resident entries per row in iterate

// ---------------- static device scratch (no runtime allocation) ----------------
static __device__ float    d_rbA[NB * NL];              // -0.5*||pos||^2
static __device__ float    d_cbA[NB * NL];              // lw - 0.5*||pos||^2
static __device__ float    d_rbC[NB * NL];              // -0.5*||tpos||^2
static __device__ float    d_cbC[NB * NL];              // lw + f - 0.5*||pos||^2 (after iterate)
static __device__ int      d_scnt[NB * NL];             // nnz per row (<= CAP2)
static __device__ float          d_svalT[(size_t)NB * CAP2 * NL];   // transposed lists
static __device__ unsigned short d_scolT[(size_t)NB * CAP2 * NL];
static __device__ unsigned d_MbEnc[NB];                 // encoded per-batch shift max(lw+f)
static __device__ float    d_gw[NB * NL];               // g * exp(tlw) partials
// fp16 hi/lo splits of pos / tpos (3-term HMMA GEMM)
static __device__ __align__(16) __half d_pH[NB * NL * ND];
static __device__ __align__(16) __half d_pL[NB * NL * ND];
static __device__ __align__(16) __half d_tH[NB * NL * ND];
static __device__ __align__(16) __half d_tL[NB * NL * ND];

// ---------------- helpers ----------------
__device__ __forceinline__ unsigned fenc(float f) {
    unsigned u = __float_as_uint(f);
    return (u & 0x80000000u) ? ~u : (u | 0x80000000u);
}
__device__ __forceinline__ float fdec(unsigned e) {
    return __uint_as_float((e & 0x80000000u) ? (e ^ 0x80000000u) : ~e);
}
__device__ __forceinline__ uint32_t smem_u32(const void* p) {
    uint32_t a;
    asm("{ .reg .u64 t; cvta.to.shared.u64 t, %1; cvt.u32.u64 %0, t; }" : "=r"(a) : "l"(p));
    return a;
}
#define SW128(o) ((o) ^ (((o) >> 3) & 0x70))

__device__ __forceinline__ void ldm_x4(unsigned* r, uint32_t addr) {
    asm volatile("ldmatrix.sync.aligned.m8n8.x4.shared.b16 {%0,%1,%2,%3}, [%4];"
                 : "=r"(r[0]), "=r"(r[1]), "=r"(r[2]), "=r"(r[3]) : "r"(addr));
}
__device__ __forceinline__ void mma16816(float* d, const unsigned* a, const unsigned* b) {
    asm("mma.sync.aligned.m16n8k16.row.col.f32.f16.f16.f32 "
        "{%0,%1,%2,%3}, {%4,%5,%6,%7}, {%8,%9}, {%0,%1,%2,%3};"
        : "+f"(d[0]), "+f"(d[1]), "+f"(d[2]), "+f"(d[3])
        : "r"(a[0]), "r"(a[1]), "r"(a[2]), "r"(a[3]), "r"(b[0]), "r"(b[1]));
}
__device__ __forceinline__ void cp16(uint32_t smem_dst, const void* gsrc) {
    asm volatile("cp.async.cg.shared.global [%0], [%1], 16;"
                 :: "r"(smem_dst), "l"(gsrc) : "memory");
}
#define CP_COMMIT() asm volatile("cp.async.commit_group;" ::: "memory")
#define CP_WAIT1()  asm volatile("cp.async.wait_group 1;" ::: "memory")

// ---------------- dynamic smem layout (bytes from 1024-aligned base) ----------------
#define SM_AH    0            // 128x64 half = 16384
#define SM_AL    16384
#define SM_BH0   32768
#define SM_BL0   49152
#define SM_BH1   65536
#define SM_BL1   81920
#define SM_CBS0  98304        // 128 f32
#define SM_CBS1  98816
#define SM_C     99328        // 128*4 int (per-quarter counts) = 2048
#define SM_BS    101376       // 128 int
#define SM_PS    101888       // 4*128 f32 = 2048
#define SM_SVAL  103936       // 128*CAP2 f32 = 20480
#define SM_SCOL  124416       // 128*CAP2 u16 = 10240
#define SM_END   134656
#define SMEMSZ   (SM_END + 1024)

// ---------------- prep: norms, biases, fp16 hi/lo splits ----------------
__global__ void prep_kernel(const float* __restrict__ pos,
                            const float* __restrict__ lw,
                            const float* __restrict__ tpos)
{
    int i = blockIdx.x * blockDim.x + threadIdx.x;
    if (i >= NB * NL) return;
    const float* p = pos  + (size_t)i * ND;
    const float* t = tpos + (size_t)i * ND;
    float sp = 0.f, st = 0.f;
#pragma unroll
    for (int d = 0; d < ND; d++) {
        float x = p[d], y = t[d];
        sp += x * x; st += y * y;
        __half xh = __float2half_rn(x);
        __half yh = __float2half_rn(y);
        d_pH[(size_t)i * ND + d] = xh;
        d_pL[(size_t)i * ND + d] = __float2half_rn(x - __half2float(xh));
        d_tH[(size_t)i * ND + d] = yh;
        d_tL[(size_t)i * ND + d] = __float2half_rn(y - __half2float(yh));
    }
    d_rbA[i] = -0.5f * sp;
    d_cbA[i] = lw[i] - 0.5f * sp;
    d_rbC[i] = -0.5f * st;
}

// ---------------- HMMA score pass (cp.async double-buffered B) ----------------
// Block = 128-row stripe of batch b, 16 warps in 4x4 (rowgroup x colquarter); 16 col tiles.
// P = A.B^T + rowbias + colbias via mma.sync m16n8k16, 3-term fp16 split, fp32 accum.
// PHASE 0 (self): threshold vs lw_r - STHRESH, shift lw_r, deterministic quad-ballot
//   compaction into per-row lists (diag pinned slot 0).
// PHASE 1 (cross): per-row running sums of exp(P - Mb) -> d_gw.
template <int PHASE>
__global__ __launch_bounds__(512, 1) void score_hmma(const float* __restrict__ W)  // lw / tlw
{
    extern __shared__ char smraw[];
    char* sm = (char*)((((uintptr_t)smraw) + 1023) & ~(uintptr_t)1023);
    const uint32_t sb = smem_u32(sm);

    const int b   = blockIdx.y;
    const int rt  = blockIdx.x * 128;
    const int tid = threadIdx.x;
    const int wid = tid >> 5;
    const int lane = tid & 31;
    const int cq  = wid & 3;           // column quarter (cols [cq*32, cq*32+32))
    const int mb  = (wid >> 2) * 32;   // row group base
    const int g   = lane >> 2;         // quad id
    const int q   = lane & 3;          // lane in quad

    int*   s_c  = (int*)(sm + SM_C);    // [row][quarter]
    int*   s_bs = (int*)(sm + SM_BS);
    float* s_ps = (float*)(sm + SM_PS); // [quarter][row]
    float* sval = (float*)(sm + SM_SVAL);
    unsigned short* scol = (unsigned short*)(sm + SM_SCOL);

    if (PHASE == 0 && tid < 128) s_bs[tid] = 0;

    const char* Bh = (const char*)(d_pH + (size_t)b * NL * ND);
    const char* Bl = (const char*)(d_pL + (size_t)b * NL * ND);
    const float* cb = PHASE ? d_cbC : d_cbA;

    // stage A (stripe rows, hi+lo fp16) once, SW128 swizzled (regular stores)
    {
        const char* Ah = (const char*)((PHASE ? d_tH : d_pH) + ((size_t)b * NL + rt) * ND);
        const char* Al = (const char*)((PHASE ? d_tL : d_pL) + ((size_t)b * NL + rt) * ND);
        for (int i = tid; i < 1024; i += 512) {
            int r = i >> 3, s8 = i & 7;
            uint32_t off = (uint32_t)(r * 128 + s8 * 16);
            uint32_t sw = SW128(off);
            *(uint4*)(sm + SM_AH + sw) = *(const uint4*)(Ah + off);
            *(uint4*)(sm + SM_AL + sw) = *(const uint4*)(Al + off);
        }
    }

    // prologue: stage B tile 0 into buffer 0 via cp.async
    {
        const char* bh0 = Bh;   // ct = 0
        const char* bl0 = Bl;
        for (int i = tid; i < 1024; i += 512) {
            int r = i >> 3, s8 = i & 7;
            uint32_t off = (uint32_t)(r * 128 + s8 * 16);
            uint32_t sw = SW128(off);
            cp16(sb + SM_BH0 + sw, bh0 + off);
            cp16(sb + SM_BL0 + sw, bl0 + off);
        }
        if (tid < 32) cp16(sb + SM_CBS0 + tid * 16, cb + b * NL + tid * 4);
    }
    CP_COMMIT();

    // per-thread row slots: s = mt*2 + rh -> local row mb + mt*16 + rh*8 + g
    int rloc[4]; float rbv4[4], lwr4[4];
    float Mb = 0.f;
    if (PHASE == 1) Mb = fdec(d_MbEnc[b]);
    const float* rb = PHASE ? d_rbC : d_rbA;
#pragma unroll
    for (int s = 0; s < 4; s++) {
        int rl = mb + (s >> 1) * 16 + (s & 1) * 8 + g;
        rloc[s] = rl;
        float r0 = rb[b * NL + rt + rl];
        if (PHASE == 0) { lwr4[s] = W[b * NL + rt + rl]; rbv4[s] = r0; }
        else            { rbv4[s] = r0 - Mb; }
    }

    // per-lane ldmatrix address components
    const int arow = lane & 15;               // + mb + mt*16
    const int acs  = lane >> 4;               // A chunk select
    const int nrow = ((lane >> 4) << 3) + (lane & 7);   // + cq*32 + np*16
    const int bcs  = (lane >> 3) & 1;         // B chunk select

    float rs[4] = {0.f, 0.f, 0.f, 0.f};       // PHASE 1 per-row running sums

    for (int t = 0; t < 16; t++) {
        const int ct = t * 128;
        // issue next tile's staging into the other buffer (overlaps with compute below)
        if (t < 15) {
            const int nb_ = (t + 1) & 1;
            const uint32_t bhB = nb_ ? SM_BH1 : SM_BH0;
            const uint32_t blB = nb_ ? SM_BL1 : SM_BL0;
            const char* bhs = Bh + (size_t)(ct + 128) * 128;
            const char* bls = Bl + (size_t)(ct + 128) * 128;
            for (int i = tid; i < 1024; i += 512) {
                int r = i >> 3, s8 = i & 7;
                uint32_t off = (uint32_t)(r * 128 + s8 * 16);
                uint32_t sw = SW128(off);
                cp16(sb + bhB + sw, bhs + off);
                cp16(sb + blB + sw, bls + off);
            }
            if (tid < 32)
                cp16(sb + (nb_ ? SM_CBS1 : SM_CBS0) + tid * 16, cb + b * NL + ct + 128 + tid * 4);
        }
        CP_COMMIT();
        CP_WAIT1();            // tile t's group complete
        __syncthreads();

        const uint32_t bhB = (t & 1) ? SM_BH1 : SM_BH0;
        const uint32_t blB = (t & 1) ? SM_BL1 : SM_BL0;
        const float* cbs = (const float*)(sm + ((t & 1) ? SM_CBS1 : SM_CBS0));

        // -------- mainloop: 3-term HMMA, M=32 N=32 per warp --------
        float acc[2][4][4];
#pragma unroll
        for (int mt = 0; mt < 2; mt++)
#pragma unroll
            for (int nt = 0; nt < 4; nt++)
#pragma unroll
                for (int e = 0; e < 4; e++) acc[mt][nt][e] = 0.f;

#pragma unroll
        for (int kc = 0; kc < 8; kc += 2) {
            unsigned ah[2][4], al[2][4];
#pragma unroll
            for (int mt = 0; mt < 2; mt++) {
                uint32_t off = (uint32_t)((mb + mt * 16 + arow) * 128 + (kc + acs) * 16);
                uint32_t sw = SW128(off);
                ldm_x4(ah[mt], sb + SM_AH + sw);
                ldm_x4(al[mt], sb + SM_AL + sw);
            }
#pragma unroll
            for (int np = 0; np < 2; np++) {
                unsigned bh4[4], bl4[4];
                uint32_t off = (uint32_t)((cq * 32 + np * 16 + nrow) * 128 + (kc + bcs) * 16);
                uint32_t sw = SW128(off);
                ldm_x4(bh4, sb + bhB + sw);
                ldm_x4(bl4, sb + blB + sw);
#pragma unroll
                for (int mt = 0; mt < 2; mt++)
#pragma unroll
                    for (int t2 = 0; t2 < 2; t2++) {
                        float* d = acc[mt][np * 2 + t2];
                        mma16816(d, ah[mt], &bh4[2 * t2]);   // hh
                        mma16816(d, ah[mt], &bl4[2 * t2]);   // hl
                        mma16816(d, al[mt], &bh4[2 * t2]);   // lh
                    }
            }
        }

        // -------- per-tile epilogue --------
        if (PHASE == 0) {
            // count phase (+ diag pin to slot 0)
            int cnt[4] = {0, 0, 0, 0};
#pragma unroll
            for (int mt = 0; mt < 2; mt++)
#pragma unroll
                for (int rh = 0; rh < 2; rh++) {
                    const int s = mt * 2 + rh;
                    const int grow = rt + rloc[s];
                    const float thr = lwr4[s] - STHRESH;
#pragma unroll
                    for (int nt = 0; nt < 4; nt++)
#pragma unroll
                        for (int c = 0; c < 2; c++) {
                            int cl = cq * 32 + nt * 8 + 2 * q + c;
                            float v = acc[mt][nt][rh * 2 + c] + rbv4[s] + cbs[cl];
                            int gcol = ct + cl;
                            bool isd  = (gcol == grow);
                            bool keep = (v > thr) && !isd;
                            unsigned bm = __ballot_sync(0xFFFFFFFFu, keep);
                            if (isd) {
                                sval[rloc[s] * CAP2] = __expf(v - lwr4[s]);
                                scol[rloc[s] * CAP2] = (unsigned short)gcol;
                            }
                            cnt[s] += __popc((bm >> (g * 4)) & 0xFu);
                        }
                }
            if (q == 0) {
#pragma unroll
                for (int s = 0; s < 4; s++) s_c[rloc[s] * 4 + cq] = cnt[s];
            }
            __syncthreads();
            // write phase: quarter-ordered deterministic offsets
            int ws[4];
#pragma unroll
            for (int s = 0; s < 4; s++) {
                int off0 = 1 + s_bs[rloc[s]];
#pragma unroll
                for (int qq = 0; qq < 4; qq++)
                    if (qq < cq) off0 += s_c[rloc[s] * 4 + qq];
                ws[s] = off0;
            }
#pragma unroll
            for (int mt = 0; mt < 2; mt++)
#pragma unroll
                for (int rh = 0; rh < 2; rh++) {
                    const int s = mt * 2 + rh;
                    const int grow = rt + rloc[s];
                    const float thr = lwr4[s] - STHRESH;
#pragma unroll
                    for (int nt = 0; nt < 4; nt++)
#pragma unroll
                        for (int c = 0; c < 2; c++) {
                            int cl = cq * 32 + nt * 8 + 2 * q + c;
                            float v = acc[mt][nt][rh * 2 + c] + rbv4[s] + cbs[cl];
                            int gcol = ct + cl;
                            bool keep = (v > thr) && (gcol != grow);
                            unsigned bm = __ballot_sync(0xFFFFFFFFu, keep);
                            unsigned nib = (bm >> (g * 4)) & 0xFu;
                            if (keep) {
                                int pos = ws[s] + __popc(nib & ((1u << q) - 1u));
                                if (pos < CAP2) {
                                    sval[rloc[s] * CAP2 + pos] = __expf(v - lwr4[s]);
                                    scol[rloc[s] * CAP2 + pos] = (unsigned short)gcol;
                                }
                            }
                            ws[s] += __popc(nib);
                        }
                }
            __syncthreads();
            if (cq == 0 && q == 0) {
#pragma unroll
                for (int s = 0; s < 4; s++)
                    s_bs[rloc[s]] += s_c[rloc[s] * 4 + 0] + s_c[rloc[s] * 4 + 1]
                                   + s_c[rloc[s] * 4 + 2] + s_c[rloc[s] * 4 + 3];
            }
            __syncthreads();
        } else {
#pragma unroll
            for (int mt = 0; mt < 2; mt++)
#pragma unroll
                for (int rh = 0; rh < 2; rh++) {
                    const int s = mt * 2 + rh;
#pragma unroll
                    for (int nt = 0; nt < 4; nt++)
#pragma unroll
                        for (int c = 0; c < 2; c++) {
                            int cl = cq * 32 + nt * 8 + 2 * q + c;
                            rs[s] += __expf(acc[mt][nt][rh * 2 + c] + rbv4[s] + cbs[cl]);
                        }
                }
            __syncthreads();   // all cbs/B reads done before next stage overwrites
        }
    }

    // -------- final epilogue --------
    if (PHASE == 0) {
        // coalesced transposed write of the lists
        for (int idx = tid; idx < 128 * CAP2; idx += 512) {
            int j  = idx >> 7;
            int rr = idx & 127;
            int c = 1 + s_bs[rr]; if (c > CAP2) c = CAP2;
            size_t o = ((size_t)b * CAP2 + j) * NL + rt + rr;
            d_svalT[o] = (j < c) ? sval[rr * CAP2 + j] : 0.f;
            d_scolT[o] = (j < c) ? scol[rr * CAP2 + j] : (unsigned short)0;
        }
        if (tid < 128) {
            int c = 1 + s_bs[tid]; if (c > CAP2) c = CAP2;
            d_scnt[b * NL + rt + tid] = c;
        }
    } else {
#pragma unroll
        for (int s = 0; s < 4; s++) {
            float v = rs[s];
            v += __shfl_xor_sync(0xFFFFFFFFu, v, 1);
            v += __shfl_xor_sync(0xFFFFFFFFu, v, 2);
            if (q == 0) s_ps[cq * 128 + rloc[s]] = v;
        }
        __syncthreads();
        if (tid < 128) {
            float ssum = s_ps[tid] + s_ps[128 + tid] + s_ps[256 + tid] + s_ps[384 + tid];
            float gg = -(Mb + __logf(ssum));
            d_gw[b * NL + rt + tid] = gg * __expf(W[b * NL + rt + tid]);
        }
    }
}

// ---------------- iterations: one block per batch, double-buffered us, 1 sync/iter ----------------
__global__ __launch_bounds__(1024, 1) void iterate_kernel(const float* __restrict__ lw)
{
    const int b   = blockIdx.x;
    const int tid = threadIdx.x;
    __shared__ float us[2][NL];         // double-buffered exp(f)
    __shared__ unsigned conv;
    __shared__ unsigned mbred;

    if (tid == 0) { conv = 0u; mbred = 0u; }

    const int r0 = tid, r1 = tid + 1024;
    const float lw0 = lw[b * NL + r0];
    const float lw1 = lw[b * NL + r1];
    const float m0 = lw0, m1 = lw1;     // shift = lw_r (matches sparse-build shift)
    const int   n0 = d_scnt[b * NL + r0];
    const int   n1 = d_scnt[b * NL + r1];

    float v0[RMAX], v1[RMAX];
    int   cp0[RMAX / 2], cp1[RMAX / 2];

    {
        int ctmp0[RMAX], ctmp1[RMAX];
#pragma unroll
        for (int j = 0; j < RMAX; j++) {
            size_t i0 = ((size_t)b * CAP2 + j) * NL + r0;
            size_t i1 = ((size_t)b * CAP2 + j) * NL + r1;
            bool k0 = (j < n0), k1 = (j < n1);
            v0[j]    = k0 ? d_svalT[i0] : 0.f;
            ctmp0[j] = k0 ? (int)d_scolT[i0] : 0;
            v1[j]    = k1 ? d_svalT[i1] : 0.f;
            ctmp1[j] = k1 ? (int)d_scolT[i1] : 0;
        }
#pragma unroll
        for (int h = 0; h < RMAX / 2; h++) {
            cp0[h] = ctmp0[2 * h] | (ctmp0[2 * h + 1] << 16);
            cp1[h] = ctmp1[2 * h] | (ctmp1[2 * h + 1] << 16);
        }
    }

    float f0 = 0.f, f1 = 0.f;
    us[0][r0] = 1.f;                    // exp(0)
    us[0][r1] = 1.f;
    __syncthreads();

    for (int it = 0; it < NITER; it++) {
        const float* uc = us[it & 1];
        float* un = us[(it & 1) ^ 1];

        float s0 = 0.f, s1 = 0.f;
#pragma unroll
        for (int h = 0; h < RMAX / 2; h++) {
            int p0 = cp0[h], p1 = cp1[h];
            s0 = fmaf(v0[2 * h],     uc[p0 & 0xFFFF], s0);
            s0 = fmaf(v0[2 * h + 1], uc[p0 >> 16],    s0);
            s1 = fmaf(v1[2 * h],     uc[p1 & 0xFFFF], s1);
            s1 = fmaf(v1[2 * h + 1], uc[p1 >> 16],    s1);
        }
        for (int j = RMAX; j < n0; j++) {
            size_t idx = ((size_t)b * CAP2 + j) * NL + r0;
            s0 = fmaf(d_svalT[idx], uc[d_scolT[idx]], s0);
        }
        for (int j = RMAX; j < n1; j++) {
            size_t idx = ((size_t)b * CAP2 + j) * NL + r1;
            s1 = fmaf(d_svalT[idx], uc[d_scolT[idx]], s1);
        }

        float fn0 = 0.5f * (f0 - m0 - __logf(s0));
        float fn1 = 0.5f * (f1 - m1 - __logf(s1));
        float dmax = fmaxf(fabsf(fn0 - f0), fabsf(fn1 - f1));
        un[r0] = __expf(fn0);           // other buffer: safe while uc still being read
        un[r1] = __expf(fn1);
        f0 = fn0;
        f1 = fn1;
        __syncthreads();                // single sync: uc reads done + un visible

        if ((it & 3) == 3 && it < NITER - 1) {
#pragma unroll
            for (int off = 16; off > 0; off >>= 1)
                dmax = fmaxf(dmax, __shfl_xor_sync(0xFFFFFFFFu, dmax, off));
            if ((tid & 31) == 0) atomicMax(&conv, fenc(dmax));
            __syncthreads();
            bool stop = fdec(conv) < 1e-6f;
            __syncthreads();
            if (tid == 0) conv = 0u;
            if (stop) break;
        }
    }

    // per-batch shift for the cross pass: Mb = max_k(lw_k + f_k)
    float lf = fmaxf(lw0 + f0, lw1 + f1);
#pragma unroll
    for (int off = 16; off > 0; off >>= 1)
        lf = fmaxf(lf, __shfl_xor_sync(0xFFFFFFFFu, lf, off));
    if ((tid & 31) == 0) atomicMax(&mbred, fenc(lf));

    d_cbC[b * NL + r0] = lw0 + f0 + d_rbA[b * NL + r0];
    d_cbC[b * NL + r1] = lw1 + f1 + d_rbA[b * NL + r1];

    __syncthreads();
    if (tid == 0) d_MbEnc[b] = mbred;
}

// ---------------- deterministic final reduction ----------------
__global__ __launch_bounds__(256) void reduce_kernel(float* __restrict__ out)
{
    const int b = blockIdx.x;
    float s = 0.f;
    for (int k = threadIdx.x; k < NL; k += 256) s += d_gw[b * NL + k];
    __shared__ float red[256];
    red[threadIdx.x] = s;
    __syncthreads();
    for (int off = 128; off > 0; off >>= 1) {
        if (threadIdx.x < off) red[threadIdx.x] += red[threadIdx.x + off];
        __syncthreads();
    }
    if (threadIdx.x == 0) out[b] = red[0];
}

// ---------------- launch ----------------
extern "C" void kernel_launch(void* const* d_in, const int* in_sizes, int n_in,
                              void* d_out, int out_size)
{
    const float* pos  = (const float*)d_in[0];   // (8, 2048, 64)
    const float* lw   = (const float*)d_in[1];   // (8, 2048)
    const float* tpos = (const float*)d_in[2];   // (8, 2048, 64)
    const float* tlw  = (const float*)d_in[3];   // (8, 2048)
    float* out = (float*)d_out;                  // (8,)

    cudaFuncSetAttribute(score_hmma<0>, cudaFuncAttributeMaxDynamicSharedMemorySize, SMEMSZ);
    cudaFuncSetAttribute(score_hmma<1>, cudaFuncAttributeMaxDynamicSharedMemorySize, SMEMSZ);

    prep_kernel<<<(NB * NL + 255) / 256, 256>>>(pos, lw, tpos);

    dim3 g(NL / 128, NB);                        // 128 blocks: one wave
    score_hmma<0><<<g, 512, SMEMSZ>>>(lw);       // self scores -> sparse lists

    iterate_kernel<<<NB, 1024>>>(lw);

    score_hmma<1><<<g, 512, SMEMSZ>>>(tlw);      // cross scores -> d_gw

    reduce_kernel<<<NB, 256>>>(out);
}